// round 7
// baseline (speedup 1.0000x reference)
#include <cuda_runtime.h>
#include <math.h>

// Problem constants
#define Bb 2
#define Sq 2048
#define Dm 1024
#define Hn 16
#define Hd 64

// ---------------- scratch (static device globals: no allocation allowed) ----
__device__ float g_q[Bb * Hn * Sq * Hd];     // [B,H,S,d], pre-scaled by 1/8
__device__ float g_k[Bb * Hn * Sq * Hd];     // [B,H,S,d]
__device__ float g_v[Bb * Hn * Sq * Hd];     // [B,H,S,d]
__device__ float g_att[Bb * Sq * Dm];        // [B,S,H*d] attention output pre-Wo
__device__ unsigned char g_bucket[4096];     // bucket LUT for rp = k - q in [-2047,2047]

// ---------------- T5 relative position bucket ------------------------------
__device__ __forceinline__ int rel_bucket(int rp) {
    int ret = (rp >= 0) ? 16 : 0;
    int n = rp < 0 ? -rp : rp;
    if (n < 8) return ret + n;
    float v = logf((float)n * 0.125f) / logf(16.0f) * 8.0f;
    int vi = 8 + (int)v;
    if (vi > 15) vi = 15;
    return ret + vi;
}

__global__ void lut_kernel() {
    int i = blockIdx.x * 256 + threadIdx.x;   // 0..4095
    if (i < 4096) g_bucket[i] = (unsigned char)rel_bucket(i - 2047);
}

// past_bias writer: out layout [1,H,S,S] at d_out + B*S*D
__global__ void bias_kernel(const float* __restrict__ relb, float* __restrict__ out) {
    int q = blockIdx.x;
    int h = blockIdx.y;
    int k0 = threadIdx.x * 4;                 // 512 threads cover 2048 keys
    int lb = k0 - q + 2047;
    float4 v;
    v.x = relb[(int)g_bucket[lb + 0] * Hn + h];
    v.y = relb[(int)g_bucket[lb + 1] * Hn + h];
    v.z = relb[(int)g_bucket[lb + 2] * Hn + h];
    v.w = relb[(int)g_bucket[lb + 3] * Hn + h];
    *(float4*)(out + ((size_t)h * Sq + q) * Sq + k0) = v;
}

// ---------------- SGEMM: C[M,N] = A[M,K] @ W[N,K]^T -------------------------
// M=4096, N=1024, K=1024. Tile 128x64x16, 128 threads, 8x8 micro-tile,
// double-buffered smem with register-staged prefetch.
// csel: 0/1/2 -> scatter to g_q/g_k/g_v as [B,H,S,d]; 3 -> row-major to Cext.
// asel: 0 -> Aext; 1 -> g_att.
#define GBM 128
#define GBN 64
#define GBK 16
#define ASTR (GBM + 4)
#define BSTR (GBN + 4)

__device__ __forceinline__ void gemm_compute(
    const float* __restrict__ as, const float* __restrict__ bs,
    float acc[8][8], int ty, int tx)
{
#pragma unroll
    for (int k = 0; k < GBK; k++) {
        float a[8], b[8];
        *(float4*)&a[0] = *(const float4*)(as + k * ASTR + ty * 8);
        *(float4*)&a[4] = *(const float4*)(as + k * ASTR + ty * 8 + 4);
        *(float4*)&b[0] = *(const float4*)(bs + k * BSTR + tx * 8);
        *(float4*)&b[4] = *(const float4*)(bs + k * BSTR + tx * 8 + 4);
#pragma unroll
        for (int i = 0; i < 8; i++)
#pragma unroll
            for (int j = 0; j < 8; j++) acc[i][j] += a[i] * b[j];
    }
}

__global__ __launch_bounds__(128, 3)
void sgemm_kernel(const float* __restrict__ Aext, const float* __restrict__ W,
                  float* __restrict__ Cext, int asel, int csel, float scale) {
    const int Kdim = 1024;
    __shared__ float As[2][GBK][ASTR];   // [k][m]
    __shared__ float Bs[2][GBK][BSTR];   // [k][n]

    const float* A = asel ? g_att : Aext;
    const int tid = threadIdx.x;
    const int tx = tid & 7;    // n dir (8)  -> n = tx*8
    const int ty = tid >> 3;   // m dir (16) -> m = ty*8
    const int bx = blockIdx.x; // N/64 = 16
    const int by = blockIdx.y; // M/128 = 32

    const float* Ab = A + (size_t)by * GBM * Kdim;
    const float* Wb = W + (size_t)bx * GBN * Kdim;

    const int lr = tid >> 2;        // 0..31
    const int lc = (tid & 3) * 4;   // 0,4,8,12

    float acc[8][8];
#pragma unroll
    for (int i = 0; i < 8; i++)
#pragma unroll
        for (int j = 0; j < 8; j++) acc[i][j] = 0.0f;

    float4 ra0, ra1, ra2, ra3, rb0, rb1;

#define LDTILE(KT)                                                        \
    ra0 = *(const float4*)(Ab + (size_t)(lr      ) * Kdim + (KT) + lc);   \
    ra1 = *(const float4*)(Ab + (size_t)(lr + 32) * Kdim + (KT) + lc);    \
    ra2 = *(const float4*)(Ab + (size_t)(lr + 64) * Kdim + (KT) + lc);    \
    ra3 = *(const float4*)(Ab + (size_t)(lr + 96) * Kdim + (KT) + lc);    \
    rb0 = *(const float4*)(Wb + (size_t)(lr      ) * Kdim + (KT) + lc);   \
    rb1 = *(const float4*)(Wb + (size_t)(lr + 32) * Kdim + (KT) + lc);

#define STTILE(BUF)                                                                                  \
    As[BUF][lc+0][lr   ] = ra0.x; As[BUF][lc+1][lr   ] = ra0.y;                                      \
    As[BUF][lc+2][lr   ] = ra0.z; As[BUF][lc+3][lr   ] = ra0.w;                                      \
    As[BUF][lc+0][lr+32] = ra1.x; As[BUF][lc+1][lr+32] = ra1.y;                                      \
    As[BUF][lc+2][lr+32] = ra1.z; As[BUF][lc+3][lr+32] = ra1.w;                                      \
    As[BUF][lc+0][lr+64] = ra2.x; As[BUF][lc+1][lr+64] = ra2.y;                                      \
    As[BUF][lc+2][lr+64] = ra2.z; As[BUF][lc+3][lr+64] = ra2.w;                                      \
    As[BUF][lc+0][lr+96] = ra3.x; As[BUF][lc+1][lr+96] = ra3.y;                                      \
    As[BUF][lc+2][lr+96] = ra3.z; As[BUF][lc+3][lr+96] = ra3.w;                                      \
    Bs[BUF][lc+0][lr   ] = rb0.x; Bs[BUF][lc+1][lr   ] = rb0.y;                                      \
    Bs[BUF][lc+2][lr   ] = rb0.z; Bs[BUF][lc+3][lr   ] = rb0.w;                                      \
    Bs[BUF][lc+0][lr+32] = rb1.x; Bs[BUF][lc+1][lr+32] = rb1.y;                                      \
    Bs[BUF][lc+2][lr+32] = rb1.z; Bs[BUF][lc+3][lr+32] = rb1.w;

    // prologue: tile 0 -> buf0
    LDTILE(0);
    STTILE(0);
    __syncthreads();

    // main loop: each iter computes chunks kt, kt+16; leaves buf0 = chunk kt+32
    for (int kt = 0; kt + 2 * GBK < Kdim; kt += 2 * GBK) {
        LDTILE(kt + GBK);
        gemm_compute(&As[0][0][0], &Bs[0][0][0], acc, ty, tx);
        STTILE(1);
        __syncthreads();
        LDTILE(kt + 2 * GBK);
        gemm_compute(&As[1][0][0], &Bs[1][0][0], acc, ty, tx);
        STTILE(0);
        __syncthreads();
    }
    // epilogue: buf0 = chunk Kdim-32; load final chunk, compute both
    LDTILE(Kdim - GBK);
    gemm_compute(&As[0][0][0], &Bs[0][0][0], acc, ty, tx);
    STTILE(1);
    __syncthreads();
    gemm_compute(&As[1][0][0], &Bs[1][0][0], acc, ty, tx);

#undef LDTILE
#undef STTILE

    // writeback
    if (csel == 3) {
#pragma unroll
        for (int i = 0; i < 8; i++) {
            int m = by * GBM + ty * 8 + i;
            float* dst = Cext + (size_t)m * 1024 + bx * GBN + tx * 8;
            float4 v0, v1;
            v0.x = acc[i][0] * scale; v0.y = acc[i][1] * scale;
            v0.z = acc[i][2] * scale; v0.w = acc[i][3] * scale;
            v1.x = acc[i][4] * scale; v1.y = acc[i][5] * scale;
            v1.z = acc[i][6] * scale; v1.w = acc[i][7] * scale;
            *(float4*)dst = v0;
            *(float4*)(dst + 4) = v1;
        }
    } else {
        float* C = (csel == 0) ? g_q : (csel == 1 ? g_k : g_v);
        // GBN == 64 == Hd  =>  head index == bx, d = tx*8 .. +7 (contiguous)
#pragma unroll
        for (int i = 0; i < 8; i++) {
            int m = by * GBM + ty * 8 + i;
            int bbi = m >> 11, ssi = m & 2047;
            float* dst = C + (((size_t)bbi * Hn + bx) * Sq + ssi) * Hd + tx * 8;
            float4 v0, v1;
            v0.x = acc[i][0] * scale; v0.y = acc[i][1] * scale;
            v0.z = acc[i][2] * scale; v0.w = acc[i][3] * scale;
            v1.x = acc[i][4] * scale; v1.y = acc[i][5] * scale;
            v1.z = acc[i][6] * scale; v1.w = acc[i][7] * scale;
            *(float4*)dst = v0;
            *(float4*)(dst + 4) = v1;
        }
    }
}

// ---------------- Flash attention: 2 queries/thread, split head-dim ---------
// Block: 128 threads = 128 queries. Thread pair (lane^1) shares 2 queries;
// each thread of the pair owns half (32) of the head dim for both Q and O.
// One K/V LDS.128 feeds 8 FMAs (2 queries x 4 dims). Half dot-products are
// combined with one shfl.xor per key (commutative add -> both pair threads
// hold bitwise-identical scores, so softmax state stays consistent).
__global__ __launch_bounds__(128, 2)
void attn_kernel(const float* __restrict__ relb) {
    __shared__ float Ks[64][64];
    __shared__ float Vs[64][64];
    __shared__ float rb[32];
    __shared__ unsigned char lut[4096];

    const int tid = threadIdx.x;
    const int half = tid & 1;          // which 32-dim half of d
    const int pair = tid >> 1;         // 0..63
    const int h = blockIdx.y, b = blockIdx.z;
    const int q0 = blockIdx.x * 128 + pair * 2;   // queries q0, q0+1

    for (int i = tid; i < 4096; i += 128) lut[i] = g_bucket[i];
    if (tid < 32) rb[tid] = relb[tid * Hn + h];

    const size_t bh = (size_t)(b * Hn + h) * Sq;

    float qr[2][32];
#pragma unroll
    for (int j = 0; j < 2; j++) {
        const float4* qp = (const float4*)(g_q + (bh + (size_t)(q0 + j)) * Hd + half * 32);
#pragma unroll
        for (int i = 0; i < 8; i++) {
            float4 v = qp[i];
            qr[j][i * 4 + 0] = v.x; qr[j][i * 4 + 1] = v.y;
            qr[j][i * 4 + 2] = v.z; qr[j][i * 4 + 3] = v.w;
        }
    }
    float o[2][32];
#pragma unroll
    for (int j = 0; j < 2; j++)
#pragma unroll
        for (int i = 0; i < 32; i++) o[j][i] = 0.0f;
    float mrun[2] = {-1e30f, -1e30f};
    float lrun[2] = {0.0f, 0.0f};

    const float* Kb = g_k + bh * Hd;
    const float* Vb = g_v + bh * Hd;

    for (int kt = 0; kt < Sq; kt += 64) {
        __syncthreads();   // also covers initial lut/rb visibility
#pragma unroll
        for (int p = 0; p < 8; p++) {
            int r = (tid >> 4) + p * 8;
            int c = (tid & 15) * 4;
            *(float4*)&Ks[r][c] = *(const float4*)(Kb + (size_t)(kt + r) * Hd + c);
            *(float4*)&Vs[r][c] = *(const float4*)(Vb + (size_t)(kt + r) * Hd + c);
        }
        __syncthreads();

#pragma unroll 1
        for (int ck = 0; ck < 64; ck += 8) {
            float s[2][8];
#pragma unroll
            for (int kk = 0; kk < 8; kk++) { s[0][kk] = 0.0f; s[1][kk] = 0.0f; }

            // partial scores over this thread's 32 dims
#pragma unroll
            for (int d4 = 0; d4 < 8; d4++) {
#pragma unroll
                for (int kk = 0; kk < 8; kk++) {
                    float4 kv = *(const float4*)&Ks[ck + kk][half * 32 + d4 * 4];
                    s[0][kk] += qr[0][d4 * 4 + 0] * kv.x;
                    s[0][kk] += qr[0][d4 * 4 + 1] * kv.y;
                    s[0][kk] += qr[0][d4 * 4 + 2] * kv.z;
                    s[0][kk] += qr[0][d4 * 4 + 3] * kv.w;
                    s[1][kk] += qr[1][d4 * 4 + 0] * kv.x;
                    s[1][kk] += qr[1][d4 * 4 + 1] * kv.y;
                    s[1][kk] += qr[1][d4 * 4 + 2] * kv.z;
                    s[1][kk] += qr[1][d4 * 4 + 3] * kv.w;
                }
            }
            // combine halves (commutative add -> identical in both threads)
#pragma unroll
            for (int kk = 0; kk < 8; kk++) {
                s[0][kk] += __shfl_xor_sync(0xffffffffu, s[0][kk], 1);
                s[1][kk] += __shfl_xor_sync(0xffffffffu, s[1][kk], 1);
            }
            // relative-position bias
            int lb0 = kt + ck - q0 + 2047;
#pragma unroll
            for (int kk = 0; kk < 8; kk++) {
                s[0][kk] += rb[lut[lb0 + kk]];
                s[1][kk] += rb[lut[lb0 - 1 + kk]];
            }
            // online softmax per query
#pragma unroll
            for (int j = 0; j < 2; j++) {
                float cmax = s[j][0];
#pragma unroll
                for (int kk = 1; kk < 8; kk++) cmax = fmaxf(cmax, s[j][kk]);
                if (cmax > mrun[j]) {
                    float sc = __expf(mrun[j] - cmax);
                    mrun[j] = cmax;
                    lrun[j] *= sc;
#pragma unroll
                    for (int i = 0; i < 32; i++) o[j][i] *= sc;
                }
#pragma unroll
                for (int kk = 0; kk < 8; kk++) {
                    s[j][kk] = __expf(s[j][kk] - mrun[j]);
                    lrun[j] += s[j][kk];
                }
            }
            // P @ V over this thread's 32 dims
#pragma unroll
            for (int d4 = 0; d4 < 8; d4++) {
#pragma unroll
                for (int kk = 0; kk < 8; kk++) {
                    float4 vv = *(const float4*)&Vs[ck + kk][half * 32 + d4 * 4];
                    o[0][d4 * 4 + 0] += s[0][kk] * vv.x;
                    o[0][d4 * 4 + 1] += s[0][kk] * vv.y;
                    o[0][d4 * 4 + 2] += s[0][kk] * vv.z;
                    o[0][d4 * 4 + 3] += s[0][kk] * vv.w;
                    o[1][d4 * 4 + 0] += s[1][kk] * vv.x;
                    o[1][d4 * 4 + 1] += s[1][kk] * vv.y;
                    o[1][d4 * 4 + 2] += s[1][kk] * vv.z;
                    o[1][d4 * 4 + 3] += s[1][kk] * vv.w;
                }
            }
        }
    }

#pragma unroll
    for (int j = 0; j < 2; j++) {
        float inv = 1.0f / lrun[j];
        float* orow = g_att + ((size_t)b * Sq + (q0 + j)) * Dm + h * Hd + half * 32;
#pragma unroll
        for (int i = 0; i < 8; i++) {
            float4 v;
            v.x = o[j][i * 4 + 0] * inv; v.y = o[j][i * 4 + 1] * inv;
            v.z = o[j][i * 4 + 2] * inv; v.w = o[j][i * 4 + 3] * inv;
            ((float4*)orow)[i] = v;
        }
    }
}

// ---------------- launch -----------------------------------------------------
extern "C" void kernel_launch(void* const* d_in, const int* in_sizes, int n_in,
                              void* d_out, int out_size) {
    (void)in_sizes; (void)n_in; (void)out_size;
    const float* x  = (const float*)d_in[0];
    const float* wq = (const float*)d_in[1];
    const float* wk = (const float*)d_in[2];
    const float* wv = (const float*)d_in[3];
    const float* wo = (const float*)d_in[4];
    const float* rb = (const float*)d_in[5];
    float* out = (float*)d_out;

    // 1. bucket LUT
    lut_kernel<<<16, 256>>>();
    // 2. past_bias -> second output region [1,H,S,S]
    bias_kernel<<<dim3(Sq, Hn), 512>>>(rb, out + (size_t)Bb * Sq * Dm);
    // 3. Q/K/V projections (Q fused with 1/sqrt(64) scale), scattered to [B,H,S,d]
    dim3 gg(Dm / GBN, (Bb * Sq) / GBM);   // (16, 32)
    sgemm_kernel<<<gg, 128>>>(x, wq, nullptr, 0, 0, 0.125f);
    sgemm_kernel<<<gg, 128>>>(x, wk, nullptr, 0, 1, 1.0f);
    sgemm_kernel<<<gg, 128>>>(x, wv, nullptr, 0, 2, 1.0f);
    // 4. flash attention with fused relative-position bias -> g_att [B,S,H*d]
    attn_kernel<<<dim3(Sq / 128, Hn, Bb), 128>>>(rb);
    // 5. output projection -> first output region [B,S,D]
    sgemm_kernel<<<gg, 128>>>(nullptr, wo, out, 1, 3, 1.0f);
}

// round 9
// speedup vs baseline: 1.3492x; 1.3492x over previous
#include <cuda_runtime.h>
#include <cuda_bf16.h>
#include <math.h>
#include <stdint.h>

// Problem constants
#define Bb 2
#define Sq 2048
#define Dm 1024
#define Hn 16
#define Hd 64
#define MM (Dm * Dm)

// ---------------- scratch (static device globals: no allocation allowed) ----
__device__ float g_q[Bb * Hn * Sq * Hd];     // [B,H,S,d], pre-scaled by 1/8
__device__ float g_k[Bb * Hn * Sq * Hd];     // [B,H,S,d]
__device__ float g_v[Bb * Hn * Sq * Hd];     // [B,H,S,d]
__device__ float g_att[Bb * Sq * Dm];        // [B,S,H*d] attention output pre-Wo
__device__ unsigned char g_bucket[4096];     // bucket LUT
// split-bf16 operands
__device__ __nv_bfloat16 g_ah[Bb * Sq * Dm]; // activation hi
__device__ __nv_bfloat16 g_al[Bb * Sq * Dm]; // activation lo
__device__ __nv_bfloat16 g_wh[4 * MM];       // weights hi (q,k,v,o)
__device__ __nv_bfloat16 g_wl[4 * MM];       // weights lo

// ================= warp-MMA helpers (sm_80+ PTX, valid on plain sm_103) =====
__device__ __forceinline__ uint32_t smem_u32(const void* p) {
    uint32_t a;
    asm("{ .reg .u64 t; cvta.to.shared.u64 t, %1; cvt.u32.u64 %0, t; }" : "=r"(a) : "l"(p));
    return a;
}
__device__ __forceinline__ void ldsm_x4(uint32_t r[4], uint32_t addr) {
    asm volatile("ldmatrix.sync.aligned.m8n8.x4.shared.b16 {%0,%1,%2,%3}, [%4];"
                 : "=r"(r[0]), "=r"(r[1]), "=r"(r[2]), "=r"(r[3]) : "r"(addr));
}
__device__ __forceinline__ void mma16816(float c[4], const uint32_t a[4], const uint32_t b[2]) {
    asm volatile(
        "mma.sync.aligned.m16n8k16.row.col.f32.bf16.bf16.f32 "
        "{%0,%1,%2,%3}, {%4,%5,%6,%7}, {%8,%9}, {%0,%1,%2,%3};"
        : "+f"(c[0]), "+f"(c[1]), "+f"(c[2]), "+f"(c[3])
        : "r"(a[0]), "r"(a[1]), "r"(a[2]), "r"(a[3]), "r"(b[0]), "r"(b[1]));
}

// ---------------- T5 relative position bucket ------------------------------
__device__ __forceinline__ int rel_bucket(int rp) {
    int ret = (rp >= 0) ? 16 : 0;
    int n = rp < 0 ? -rp : rp;
    if (n < 8) return ret + n;
    float v = logf((float)n * 0.125f) / logf(16.0f) * 8.0f;
    int vi = 8 + (int)v;
    if (vi > 15) vi = 15;
    return ret + vi;
}

__global__ void lut_kernel() {
    int i = blockIdx.x * 256 + threadIdx.x;
    if (i < 4096) g_bucket[i] = (unsigned char)rel_bucket(i - 2047);
}

__global__ void bias_kernel(const float* __restrict__ relb, float* __restrict__ out) {
    int q = blockIdx.x;
    int h = blockIdx.y;
    int k0 = threadIdx.x * 4;
    int lb = k0 - q + 2047;
    float4 v;
    v.x = relb[(int)g_bucket[lb + 0] * Hn + h];
    v.y = relb[(int)g_bucket[lb + 1] * Hn + h];
    v.z = relb[(int)g_bucket[lb + 2] * Hn + h];
    v.w = relb[(int)g_bucket[lb + 3] * Hn + h];
    *(float4*)(out + ((size_t)h * Sq + q) * Sq + k0) = v;
}

// ---------------- fp32 -> bf16 hi/lo split ----------------------------------
// dsel: 0 -> (g_ah, g_al); 1..4 -> (g_wh, g_wl) segment dsel-1.
// src == nullptr -> read from g_att.
__global__ void split_kernel(const float* __restrict__ src, int dsel, int n4) {
    int i = blockIdx.x * 256 + threadIdx.x;
    if (i >= n4) return;
    const float* s = src ? src : (const float*)g_att;
    __nv_bfloat16* hi = (dsel == 0) ? g_ah : (g_wh + (size_t)(dsel - 1) * MM);
    __nv_bfloat16* lo = (dsel == 0) ? g_al : (g_wl + (size_t)(dsel - 1) * MM);
    float4 v = ((const float4*)s)[i];
    float f[4] = {v.x, v.y, v.z, v.w};
    __nv_bfloat16 h[4], l[4];
#pragma unroll
    for (int j = 0; j < 4; j++) {
        h[j] = __float2bfloat16(f[j]);
        l[j] = __float2bfloat16(f[j] - __bfloat162float(h[j]));
    }
    ((__nv_bfloat162*)hi)[i * 2 + 0] = __nv_bfloat162(h[0], h[1]);
    ((__nv_bfloat162*)hi)[i * 2 + 1] = __nv_bfloat162(h[2], h[3]);
    ((__nv_bfloat162*)lo)[i * 2 + 0] = __nv_bfloat162(l[0], l[1]);
    ((__nv_bfloat162*)lo)[i * 2 + 1] = __nv_bfloat162(l[2], l[3]);
}

// ---------------- warp-MMA GEMM: C[M,N] = A[M,K] @ W[N,K]^T -----------------
// Split-bf16, 3 passes: Ah.Wh + Al.Wh + Ah.Wl, accumulated in fp32 fragments.
// Block tile 128x128x32, 256 threads (8 warps, 4Mx2N), warp tile 32x64.
// Smem rows padded to 40 bf16 (80 B) -> conflict-free ldmatrix.
// wsel: weight segment 0..3. csel: 0/1/2 scatter to g_q/g_k/g_v; 3 row-major.
#define ASTRB 80   // bytes per smem row
#define BUFB 10240 // bytes per buffer per operand (128*80)

__global__ __launch_bounds__(256)
void gemm_mma(float* __restrict__ Cext, int wsel, int csel, float scale) {
    __shared__ __nv_bfloat16 As[2][128][40];
    __shared__ __nv_bfloat16 Bs[2][128][40];

    const int tid = threadIdx.x;
    const int lane = tid & 31, warp = tid >> 5;
    const int wm = warp & 3, wn = warp >> 2;          // 4 x 2 warp grid
    const int bx = blockIdx.x, by = blockIdx.y;       // (N/128=8, M/128=32)

    const __nv_bfloat16* wh = g_wh + (size_t)wsel * MM;
    const __nv_bfloat16* wl = g_wl + (size_t)wsel * MM;
    const size_t aoff = (size_t)by * 128 * 1024;
    const size_t woff = (size_t)bx * 128 * 1024;

    const int lrow = tid >> 2;        // 0..63
    const int lq = (tid & 3) * 8;     // col element offset 0/8/16/24

    const uint32_t asb = smem_u32(&As[0][0][0]);
    const uint32_t bsb = smem_u32(&Bs[0][0][0]);
    // ldmatrix per-lane source rows/cols (see fragment mapping derivation)
    const int arow = wm * 32 + (lane & 15);
    const int acol = ((lane >> 4) & 1) * 16;               // byte offset
    const int brow = wn * 64 + ((lane >> 4) & 1) * 8 + (lane & 7);
    const int bcol = ((lane >> 3) & 1) * 16;               // byte offset

    float c[2][8][4];
#pragma unroll
    for (int mt = 0; mt < 2; mt++)
#pragma unroll
        for (int nt = 0; nt < 8; nt++)
#pragma unroll
            for (int r = 0; r < 4; r++) c[mt][nt][r] = 0.0f;

    uint4 ra0, ra1, rb0, rb1;

#define LDT(IT) do {                                                              \
    int _p = (IT) >> 5, _kc = (IT) & 31;                                          \
    const __nv_bfloat16* _pa = ((_p == 1) ? g_al : g_ah) + aoff + _kc * 32;       \
    const __nv_bfloat16* _pw = ((_p == 2) ? wl : wh) + woff + _kc * 32;           \
    ra0 = *(const uint4*)(_pa + (size_t)lrow * 1024 + lq);                        \
    ra1 = *(const uint4*)(_pa + (size_t)(lrow + 64) * 1024 + lq);                 \
    rb0 = *(const uint4*)(_pw + (size_t)lrow * 1024 + lq);                        \
    rb1 = *(const uint4*)(_pw + (size_t)(lrow + 64) * 1024 + lq);                 \
} while (0)

#define STT(BUF) do {                                                             \
    *(uint4*)&As[BUF][lrow][lq] = ra0;                                            \
    *(uint4*)&As[BUF][lrow + 64][lq] = ra1;                                       \
    *(uint4*)&Bs[BUF][lrow][lq] = rb0;                                            \
    *(uint4*)&Bs[BUF][lrow + 64][lq] = rb1;                                       \
} while (0)

    LDT(0);
    STT(0);
    __syncthreads();

    for (int it = 0; it < 96; it++) {                 // 3 passes x 32 K-chunks
        const int buf = it & 1;
        if (it < 95) LDT(it + 1);

        const uint32_t ab = asb + buf * BUFB;
        const uint32_t bb = bsb + buf * BUFB;
#pragma unroll
        for (int ks = 0; ks < 2; ks++) {              // two k16 steps per chunk
            const int kb = ks * 32;                   // byte offset of k16
            uint32_t af[2][4];
#pragma unroll
            for (int mt = 0; mt < 2; mt++)
                ldsm_x4(af[mt], ab + (uint32_t)(arow + mt * 16) * ASTRB + acol + kb);
            uint32_t bf[8][2];
#pragma unroll
            for (int nt2 = 0; nt2 < 4; nt2++) {
                uint32_t r[4];
                ldsm_x4(r, bb + (uint32_t)(brow + nt2 * 16) * ASTRB + bcol + kb);
                bf[nt2 * 2][0] = r[0]; bf[nt2 * 2][1] = r[1];
                bf[nt2 * 2 + 1][0] = r[2]; bf[nt2 * 2 + 1][1] = r[3];
            }
#pragma unroll
            for (int mt = 0; mt < 2; mt++)
#pragma unroll
                for (int nt = 0; nt < 8; nt++)
                    mma16816(c[mt][nt], af[mt], bf[nt]);
        }
        if (it < 95) STT(buf ^ 1);
        __syncthreads();
    }
#undef LDT
#undef STT

    // epilogue: thread (g = lane>>2, tg = lane&3) owns C rows g/g+8, cols tg*2..+1
    const int g = lane >> 2, tg = lane & 3;
#pragma unroll
    for (int mt = 0; mt < 2; mt++) {
#pragma unroll
        for (int nt = 0; nt < 8; nt++) {
            int m = by * 128 + wm * 32 + mt * 16 + g;
            int n = bx * 128 + wn * 64 + nt * 8 + tg * 2;
            float2 v0 = make_float2(c[mt][nt][0] * scale, c[mt][nt][1] * scale);
            float2 v1 = make_float2(c[mt][nt][2] * scale, c[mt][nt][3] * scale);
            if (csel == 3) {
                *(float2*)(Cext + (size_t)m * 1024 + n) = v0;
                *(float2*)(Cext + (size_t)(m + 8) * 1024 + n) = v1;
            } else {
                float* C = (csel == 0) ? g_q : (csel == 1 ? g_k : g_v);
                int head = n >> 6, d = n & 63;
                int bbi = m >> 11, ssi = m & 2047;
                size_t base = (((size_t)bbi * Hn + head) * Sq) * Hd + d;
                *(float2*)(C + base + (size_t)ssi * Hd) = v0;
                *(float2*)(C + base + (size_t)(ssi + 8) * Hd) = v1;
            }
        }
    }
}

// ---------------- Flash attention: 2 queries/thread, split head-dim ---------
__global__ __launch_bounds__(128, 2)
void attn_kernel(const float* __restrict__ relb) {
    __shared__ float Ks[64][64];
    __shared__ float Vs[64][64];
    __shared__ float rb[32];
    __shared__ unsigned char lut[4096];

    const int tid = threadIdx.x;
    const int half = tid & 1;
    const int pair = tid >> 1;
    const int h = blockIdx.y, b = blockIdx.z;
    const int q0 = blockIdx.x * 128 + pair * 2;

    for (int i = tid; i < 4096; i += 128) lut[i] = g_bucket[i];
    if (tid < 32) rb[tid] = relb[tid * Hn + h];

    const size_t bh = (size_t)(b * Hn + h) * Sq;

    float qr[2][32];
#pragma unroll
    for (int j = 0; j < 2; j++) {
        const float4* qp = (const float4*)(g_q + (bh + (size_t)(q0 + j)) * Hd + half * 32);
#pragma unroll
        for (int i = 0; i < 8; i++) {
            float4 v = qp[i];
            qr[j][i * 4 + 0] = v.x; qr[j][i * 4 + 1] = v.y;
            qr[j][i * 4 + 2] = v.z; qr[j][i * 4 + 3] = v.w;
        }
    }
    float o[2][32];
#pragma unroll
    for (int j = 0; j < 2; j++)
#pragma unroll
        for (int i = 0; i < 32; i++) o[j][i] = 0.0f;
    float mrun[2] = {-1e30f, -1e30f};
    float lrun[2] = {0.0f, 0.0f};

    const float* Kb = g_k + bh * Hd;
    const float* Vb = g_v + bh * Hd;

    for (int kt = 0; kt < Sq; kt += 64) {
        __syncthreads();
#pragma unroll
        for (int p = 0; p < 8; p++) {
            int r = (tid >> 4) + p * 8;
            int cc = (tid & 15) * 4;
            *(float4*)&Ks[r][cc] = *(const float4*)(Kb + (size_t)(kt + r) * Hd + cc);
            *(float4*)&Vs[r][cc] = *(const float4*)(Vb + (size_t)(kt + r) * Hd + cc);
        }
        __syncthreads();

#pragma unroll 1
        for (int ck = 0; ck < 64; ck += 8) {
            float s[2][8];
#pragma unroll
            for (int kk = 0; kk < 8; kk++) { s[0][kk] = 0.0f; s[1][kk] = 0.0f; }
#pragma unroll
            for (int d4 = 0; d4 < 8; d4++) {
#pragma unroll
                for (int kk = 0; kk < 8; kk++) {
                    float4 kv = *(const float4*)&Ks[ck + kk][half * 32 + d4 * 4];
                    s[0][kk] += qr[0][d4 * 4 + 0] * kv.x;
                    s[0][kk] += qr[0][d4 * 4 + 1] * kv.y;
                    s[0][kk] += qr[0][d4 * 4 + 2] * kv.z;
                    s[0][kk] += qr[0][d4 * 4 + 3] * kv.w;
                    s[1][kk] += qr[1][d4 * 4 + 0] * kv.x;
                    s[1][kk] += qr[1][d4 * 4 + 1] * kv.y;
                    s[1][kk] += qr[1][d4 * 4 + 2] * kv.z;
                    s[1][kk] += qr[1][d4 * 4 + 3] * kv.w;
                }
            }
#pragma unroll
            for (int kk = 0; kk < 8; kk++) {
                s[0][kk] += __shfl_xor_sync(0xffffffffu, s[0][kk], 1);
                s[1][kk] += __shfl_xor_sync(0xffffffffu, s[1][kk], 1);
            }
            int lb0 = kt + ck - q0 + 2047;
#pragma unroll
            for (int kk = 0; kk < 8; kk++) {
                s[0][kk] += rb[lut[lb0 + kk]];
                s[1][kk] += rb[lut[lb0 - 1 + kk]];
            }
#pragma unroll
            for (int j = 0; j < 2; j++) {
                float cmax = s[j][0];
#pragma unroll
                for (int kk = 1; kk < 8; kk++) cmax = fmaxf(cmax, s[j][kk]);
                if (cmax > mrun[j]) {
                    float sc = __expf(mrun[j] - cmax);
                    mrun[j] = cmax;
                    lrun[j] *= sc;
#pragma unroll
                    for (int i = 0; i < 32; i++) o[j][i] *= sc;
                }
#pragma unroll
                for (int kk = 0; kk < 8; kk++) {
                    s[j][kk] = __expf(s[j][kk] - mrun[j]);
                    lrun[j] += s[j][kk];
                }
            }
#pragma unroll
            for (int d4 = 0; d4 < 8; d4++) {
#pragma unroll
                for (int kk = 0; kk < 8; kk++) {
                    float4 vv = *(const float4*)&Vs[ck + kk][half * 32 + d4 * 4];
                    o[0][d4 * 4 + 0] += s[0][kk] * vv.x;
                    o[0][d4 * 4 + 1] += s[0][kk] * vv.y;
                    o[0][d4 * 4 + 2] += s[0][kk] * vv.z;
                    o[0][d4 * 4 + 3] += s[0][kk] * vv.w;
                    o[1][d4 * 4 + 0] += s[1][kk] * vv.x;
                    o[1][d4 * 4 + 1] += s[1][kk] * vv.y;
                    o[1][d4 * 4 + 2] += s[1][kk] * vv.z;
                    o[1][d4 * 4 + 3] += s[1][kk] * vv.w;
                }
            }
        }
    }

#pragma unroll
    for (int j = 0; j < 2; j++) {
        float inv = 1.0f / lrun[j];
        float* orow = g_att + ((size_t)b * Sq + (q0 + j)) * Dm + h * Hd + half * 32;
#pragma unroll
        for (int i = 0; i < 8; i++) {
            float4 v;
            v.x = o[j][i * 4 + 0] * inv; v.y = o[j][i * 4 + 1] * inv;
            v.z = o[j][i * 4 + 2] * inv; v.w = o[j][i * 4 + 3] * inv;
            ((float4*)orow)[i] = v;
        }
    }
}

// ---------------- launch -----------------------------------------------------
extern "C" void kernel_launch(void* const* d_in, const int* in_sizes, int n_in,
                              void* d_out, int out_size) {
    (void)in_sizes; (void)n_in; (void)out_size;
    const float* x  = (const float*)d_in[0];
    const float* wq = (const float*)d_in[1];
    const float* wk = (const float*)d_in[2];
    const float* wv = (const float*)d_in[3];
    const float* wo = (const float*)d_in[4];
    const float* rb = (const float*)d_in[5];
    float* out = (float*)d_out;

    // 1. bucket LUT + past_bias
    lut_kernel<<<16, 256>>>();
    bias_kernel<<<dim3(Sq, Hn), 512>>>(rb, out + (size_t)Bb * Sq * Dm);

    // 2. split activations and weights into bf16 hi/lo
    split_kernel<<<4096, 256>>>(x, 0, Bb * Sq * Dm / 4);
    split_kernel<<<1024, 256>>>(wq, 1, MM / 4);
    split_kernel<<<1024, 256>>>(wk, 2, MM / 4);
    split_kernel<<<1024, 256>>>(wv, 3, MM / 4);
    split_kernel<<<1024, 256>>>(wo, 4, MM / 4);

    // 3. Q/K/V projections (warp-MMA split-bf16), scattered to [B,H,S,d]
    dim3 gg(Dm / 128, (Bb * Sq) / 128);   // (8, 32)
    gemm_mma<<<gg, 256>>>(nullptr, 0, 0, 0.125f);
    gemm_mma<<<gg, 256>>>(nullptr, 1, 1, 1.0f);
    gemm_mma<<<gg, 256>>>(nullptr, 2, 2, 1.0f);

    // 4. flash attention -> g_att [B,S,H*d]
    attn_kernel<<<dim3(Sq / 128, Hn, Bb), 128>>>(rb);

    // 5. split attention output, then output projection -> d_out [B,S,D]
    split_kernel<<<4096, 256>>>(nullptr, 0, Bb * Sq * Dm / 4);
    gemm_mma<<<gg, 256>>>(out, 3, 3, 1.0f);
}

// round 10
// speedup vs baseline: 2.4410x; 1.8092x over previous
#include <cuda_runtime.h>
#include <cuda_bf16.h>
#include <math.h>
#include <stdint.h>

// Problem constants
#define Bb 2
#define Sq 2048
#define Dm 1024
#define Hn 16
#define Hd 64
#define MM (Dm * Dm)

// ---------------- scratch (static device globals: no allocation allowed) ----
__device__ unsigned char g_bucket[4096];      // bucket LUT for rp+2047
__device__ __nv_bfloat16 g_ah[Bb * Sq * Dm];  // activation hi (x, later attn out)
__device__ __nv_bfloat16 g_al[Bb * Sq * Dm];  // activation lo
__device__ __nv_bfloat16 g_wh[4 * MM];        // weights hi (q,k,v,o)
__device__ __nv_bfloat16 g_wl[4 * MM];        // weights lo
__device__ __nv_bfloat16 g_qh[Bb * Hn * Sq * Hd];  // Q hi [B,H,S,d], pre-scaled 1/8
__device__ __nv_bfloat16 g_ql[Bb * Hn * Sq * Hd];
__device__ __nv_bfloat16 g_kh[Bb * Hn * Sq * Hd];
__device__ __nv_bfloat16 g_kl[Bb * Hn * Sq * Hd];
__device__ __nv_bfloat16 g_vh[Bb * Hn * Sq * Hd];
__device__ __nv_bfloat16 g_vl[Bb * Hn * Sq * Hd];

// ================= PTX helpers (sm_80+ baseline, valid on plain sm_103) =====
__device__ __forceinline__ uint32_t smem_u32(const void* p) {
    uint32_t a;
    asm("{ .reg .u64 t; cvta.to.shared.u64 t, %1; cvt.u32.u64 %0, t; }" : "=r"(a) : "l"(p));
    return a;
}
__device__ __forceinline__ void ldsm_x4(uint32_t r[4], uint32_t addr) {
    asm volatile("ldmatrix.sync.aligned.m8n8.x4.shared.b16 {%0,%1,%2,%3}, [%4];"
                 : "=r"(r[0]), "=r"(r[1]), "=r"(r[2]), "=r"(r[3]) : "r"(addr));
}
__device__ __forceinline__ void ldsm_x4_t(uint32_t r[4], uint32_t addr) {
    asm volatile("ldmatrix.sync.aligned.m8n8.x4.trans.shared.b16 {%0,%1,%2,%3}, [%4];"
                 : "=r"(r[0]), "=r"(r[1]), "=r"(r[2]), "=r"(r[3]) : "r"(addr));
}
__device__ __forceinline__ void mma16816(float c[4], const uint32_t a[4], const uint32_t b[2]) {
    asm volatile(
        "mma.sync.aligned.m16n8k16.row.col.f32.bf16.bf16.f32 "
        "{%0,%1,%2,%3}, {%4,%5,%6,%7}, {%8,%9}, {%0,%1,%2,%3};"
        : "+f"(c[0]), "+f"(c[1]), "+f"(c[2]), "+f"(c[3])
        : "r"(a[0]), "r"(a[1]), "r"(a[2]), "r"(a[3]), "r"(b[0]), "r"(b[1]));
}
__device__ __forceinline__ void cpasync16(uint32_t s, const void* g) {
    asm volatile("cp.async.cg.shared.global [%0], [%1], 16;" :: "r"(s), "l"(g));
}
__device__ __forceinline__ void cp_commit() { asm volatile("cp.async.commit_group;"); }
__device__ __forceinline__ uint32_t pack_bf2(float a, float b) {
    __nv_bfloat162 t = __floats2bfloat162_rn(a, b);
    return *(uint32_t*)&t;
}

// ---------------- T5 relative position bucket ------------------------------
__device__ __forceinline__ int rel_bucket(int rp) {
    int ret = (rp >= 0) ? 16 : 0;
    int n = rp < 0 ? -rp : rp;
    if (n < 8) return ret + n;
    float v = logf((float)n * 0.125f) / logf(16.0f) * 8.0f;
    int vi = 8 + (int)v;
    if (vi > 15) vi = 15;
    return ret + vi;
}

__global__ void lut_kernel() {
    int i = blockIdx.x * 256 + threadIdx.x;
    if (i < 4096) g_bucket[i] = (unsigned char)rel_bucket(i - 2047);
}

__global__ void bias_kernel(const float* __restrict__ relb, float* __restrict__ out) {
    int q = blockIdx.x;
    int h = blockIdx.y;
    int k0 = threadIdx.x * 4;
    int lb = k0 - q + 2047;
    float4 v;
    v.x = relb[(int)g_bucket[lb + 0] * Hn + h];
    v.y = relb[(int)g_bucket[lb + 1] * Hn + h];
    v.z = relb[(int)g_bucket[lb + 2] * Hn + h];
    v.w = relb[(int)g_bucket[lb + 3] * Hn + h];
    *(float4*)(out + ((size_t)h * Sq + q) * Sq + k0) = v;
}

// ---------------- fp32 -> bf16 hi/lo split ----------------------------------
// dsel: 0 -> (g_ah, g_al); 1..4 -> (g_wh, g_wl) segment dsel-1.
__global__ void split_kernel(const float* __restrict__ src, int dsel, int n4) {
    int i = blockIdx.x * 256 + threadIdx.x;
    if (i >= n4) return;
    __nv_bfloat16* hi = (dsel == 0) ? g_ah : (g_wh + (size_t)(dsel - 1) * MM);
    __nv_bfloat16* lo = (dsel == 0) ? g_al : (g_wl + (size_t)(dsel - 1) * MM);
    float4 v = ((const float4*)src)[i];
    float f[4] = {v.x, v.y, v.z, v.w};
    __nv_bfloat16 h[4], l[4];
#pragma unroll
    for (int j = 0; j < 4; j++) {
        h[j] = __float2bfloat16(f[j]);
        l[j] = __float2bfloat16(f[j] - __bfloat162float(h[j]));
    }
    ((__nv_bfloat162*)hi)[i * 2 + 0] = __nv_bfloat162(h[0], h[1]);
    ((__nv_bfloat162*)hi)[i * 2 + 1] = __nv_bfloat162(h[2], h[3]);
    ((__nv_bfloat162*)lo)[i * 2 + 0] = __nv_bfloat162(l[0], l[1]);
    ((__nv_bfloat162*)lo)[i * 2 + 1] = __nv_bfloat162(l[2], l[3]);
}

// ---------------- warp-MMA GEMM with cp.async pipeline ----------------------
// C[M,N] = A[M,K] @ W[N,K]^T, split-bf16 3 passes (Ah.Wh + Al.Wh + Ah.Wl).
// Block tile 128x128, k16 chunks, 3-stage cp.async pipeline, 256 threads
// (8 warps 4Mx2N, warp tile 32x64). Smem rows 24 b16 (48B) -> conflict-free.
// csel: 0/1/2 -> q/k/v hi+lo bf16 scatter [B,H,S,d]; 3 -> fp32 row-major Cext.
#define GSTR 48        // smem row stride bytes
#define GSTG 6144      // bytes per stage per operand (128*48)
#define NCHUNK 192     // 3 passes x 64 k16-chunks

__global__ __launch_bounds__(256, 2)
void gemm_mma(float* __restrict__ Cext, int wsel, int csel, float scale) {
    __shared__ __nv_bfloat16 As[3][128][24];
    __shared__ __nv_bfloat16 Bs[3][128][24];

    const int tid = threadIdx.x;
    const int lane = tid & 31, warp = tid >> 5;
    const int wm = warp & 3, wn = warp >> 2;
    const int bx = blockIdx.x, by = blockIdx.y;   // (N/128=8, M/128=32)

    const __nv_bfloat16* wh = g_wh + (size_t)wsel * MM;
    const __nv_bfloat16* wl = g_wl + (size_t)wsel * MM;
    const size_t aoff = (size_t)by * 128 * 1024;
    const size_t woff = (size_t)bx * 128 * 1024;

    const int ldrow = tid >> 1;           // 0..127
    const int ldh = (tid & 1);            // 16B half of k16

    const uint32_t asb = smem_u32(&As[0][0][0]);
    const uint32_t bsb = smem_u32(&Bs[0][0][0]);
    const int arow = wm * 32 + (lane & 15);
    const int acol = ((lane >> 4) & 1) * 16;
    const int brow = wn * 64 + ((lane >> 4) & 1) * 8 + (lane & 7);
    const int bcol = ((lane >> 3) & 1) * 16;

    float c[2][8][4];
#pragma unroll
    for (int mt = 0; mt < 2; mt++)
#pragma unroll
        for (int nt = 0; nt < 8; nt++)
#pragma unroll
            for (int r = 0; r < 4; r++) c[mt][nt][r] = 0.0f;

#define ISSUE(CH) do {                                                           \
    int _p = (CH) >> 6, _kc = (CH) & 63, _st = (CH) % 3;                         \
    const __nv_bfloat16* _pa = ((_p == 1) ? g_al : g_ah) + aoff                  \
        + (size_t)ldrow * 1024 + _kc * 16 + ldh * 8;                             \
    const __nv_bfloat16* _pw = ((_p == 2) ? wl : wh) + woff                      \
        + (size_t)ldrow * 1024 + _kc * 16 + ldh * 8;                             \
    cpasync16(asb + _st * GSTG + ldrow * GSTR + ldh * 16, _pa);                  \
    cpasync16(bsb + _st * GSTG + ldrow * GSTR + ldh * 16, _pw);                  \
    cp_commit();                                                                 \
} while (0)

    ISSUE(0); ISSUE(1); ISSUE(2);

    for (int it = 0; it < NCHUNK; it++) {
        if (it < NCHUNK - 2)      asm volatile("cp.async.wait_group 2;");
        else if (it == NCHUNK - 2) asm volatile("cp.async.wait_group 1;");
        else                       asm volatile("cp.async.wait_group 0;");
        __syncthreads();

        const int st = it % 3;
        const uint32_t ab = asb + st * GSTG;
        const uint32_t bb = bsb + st * GSTG;
        uint32_t af[2][4];
#pragma unroll
        for (int mt = 0; mt < 2; mt++)
            ldsm_x4(af[mt], ab + (uint32_t)(arow + mt * 16) * GSTR + acol);
        uint32_t bf[8][2];
#pragma unroll
        for (int nt2 = 0; nt2 < 4; nt2++) {
            uint32_t r[4];
            ldsm_x4(r, bb + (uint32_t)(brow + nt2 * 16) * GSTR + bcol);
            bf[nt2 * 2][0] = r[0]; bf[nt2 * 2][1] = r[1];
            bf[nt2 * 2 + 1][0] = r[2]; bf[nt2 * 2 + 1][1] = r[3];
        }
#pragma unroll
        for (int mt = 0; mt < 2; mt++)
#pragma unroll
            for (int nt = 0; nt < 8; nt++)
                mma16816(c[mt][nt], af[mt], bf[nt]);

        __syncthreads();
        if (it + 3 < NCHUNK) ISSUE(it + 3);
    }
#undef ISSUE

    // epilogue
    const int g = lane >> 2, tg = lane & 3;
#pragma unroll
    for (int mt = 0; mt < 2; mt++) {
#pragma unroll
        for (int nt = 0; nt < 8; nt++) {
            int m = by * 128 + wm * 32 + mt * 16 + g;
            int n = bx * 128 + wn * 64 + nt * 8 + tg * 2;
            float v00 = c[mt][nt][0] * scale, v01 = c[mt][nt][1] * scale;
            float v10 = c[mt][nt][2] * scale, v11 = c[mt][nt][3] * scale;
            if (csel == 3) {
                *(float2*)(Cext + (size_t)m * 1024 + n) = make_float2(v00, v01);
                *(float2*)(Cext + (size_t)(m + 8) * 1024 + n) = make_float2(v10, v11);
            } else {
                __nv_bfloat16* Chi = (csel == 0) ? g_qh : (csel == 1 ? g_kh : g_vh);
                __nv_bfloat16* Clo = (csel == 0) ? g_ql : (csel == 1 ? g_kl : g_vl);
                int head = n >> 6, d = n & 63;
                int bbi = m >> 11, ssi = m & 2047;
                size_t base = (((size_t)bbi * Hn + head) * Sq + ssi) * Hd + d;
                __nv_bfloat162 h0 = __floats2bfloat162_rn(v00, v01);
                __nv_bfloat162 h1 = __floats2bfloat162_rn(v10, v11);
                __nv_bfloat162 l0 = __floats2bfloat162_rn(
                    v00 - __bfloat162float(h0.x), v01 - __bfloat162float(h0.y));
                __nv_bfloat162 l1 = __floats2bfloat162_rn(
                    v10 - __bfloat162float(h1.x), v11 - __bfloat162float(h1.y));
                *(__nv_bfloat162*)(Chi + base) = h0;
                *(__nv_bfloat162*)(Chi + base + 8 * Hd) = h1;
                *(__nv_bfloat162*)(Clo + base) = l0;
                *(__nv_bfloat162*)(Clo + base + 8 * Hd) = l1;
            }
        }
    }
}

// ---------------- flash attention via mma.sync -------------------------------
// Block: 128 thr = 4 warps, 64 queries (16 per warp). K-tile 64.
// QK: 3 passes split-bf16 (Kh frags reused for Qh,Ql passes).
// PV: 3 passes (PhVh + PlVh + PhVl); P built in-register from score C-frags.
// Bias: block-local precomputed float table (2112 entries).
// Smem: 4 x 64x72 bf16 tiles + bias table = 45.3 KB.
__global__ __launch_bounds__(128, 3)
void attn_mma(const float* __restrict__ relb) {
    __shared__ __nv_bfloat16 sKh[64][72];
    __shared__ __nv_bfloat16 sKl[64][72];
    __shared__ __nv_bfloat16 sVh[64][72];
    __shared__ __nv_bfloat16 sVl[64][72];
    __shared__ float biasf[2112];

    const int tid = threadIdx.x;
    const int lane = tid & 31, warp = tid >> 5;
    const int g = lane >> 2, tg = lane & 3;
    const int h = blockIdx.y, b = blockIdx.z;
    const int q0 = blockIdx.x * 64;

    // bias table: biasf[j] = bias(key - q) where j = key + 63 - (q - q0)
    for (int j = tid; j < 2112; j += 128)
        biasf[j] = relb[(int)g_bucket[j + 1984 - q0] * Hn + h];

    const size_t bh = ((size_t)b * Hn + h) * Sq;
    const int ldrow = tid >> 1;           // 0..63
    const int ldc = (tid & 1) * 4;        // uint4 index base (of 8 per row)

    // ---- stage Q into sKh/sKl, build Q fragments ----
    {
        const __nv_bfloat16* qh_g = g_qh + (bh + q0) * Hd;
        const __nv_bfloat16* ql_g = g_ql + (bh + q0) * Hd;
#pragma unroll
        for (int j = 0; j < 4; j++) {
            int cu = ldc + j;
            *(uint4*)&sKh[ldrow][cu * 8] = *(const uint4*)(qh_g + (size_t)ldrow * Hd + cu * 8);
            *(uint4*)&sKl[ldrow][cu * 8] = *(const uint4*)(ql_g + (size_t)ldrow * Hd + cu * 8);
        }
    }
    __syncthreads();

    const uint32_t khb = smem_u32(&sKh[0][0]);
    const uint32_t klb = smem_u32(&sKl[0][0]);
    const uint32_t vhb = smem_u32(&sVh[0][0]);
    const uint32_t vlb = smem_u32(&sVl[0][0]);

    uint32_t qh[4][4], ql[4][4];
    {
        const uint32_t aoff = (uint32_t)(warp * 16 + (lane & 15)) * 144 + ((lane >> 4) & 1) * 16;
#pragma unroll
        for (int ks = 0; ks < 4; ks++) {
            ldsm_x4(qh[ks], khb + aoff + ks * 32);
            ldsm_x4(ql[ks], klb + aoff + ks * 32);
        }
    }

    float onn[8][4];
#pragma unroll
    for (int nt = 0; nt < 8; nt++)
#pragma unroll
        for (int r = 0; r < 4; r++) onn[nt][r] = 0.0f;
    float mrun0 = -1e30f, mrun1 = -1e30f, lr0 = 0.0f, lr1 = 0.0f;

    const int rg = warp * 16 + g;                      // block-local row (first)
    const uint32_t kRow = ((lane >> 4) & 1) * 8 + (lane & 7);
    const uint32_t kCol = ((lane >> 3) & 1) * 16;
    const uint32_t vRow = ((lane >> 3) & 1) * 8 + (lane & 7);
    const uint32_t vCol = (uint32_t)((lane >> 4) * 8) * 2;

    const __nv_bfloat16* kh_g = g_kh + bh * Hd;
    const __nv_bfloat16* kl_g = g_kl + bh * Hd;
    const __nv_bfloat16* vh_g = g_vh + bh * Hd;
    const __nv_bfloat16* vl_g = g_vl + bh * Hd;

    for (int kt = 0; kt < Sq; kt += 64) {
        __syncthreads();   // previous compute (or Q ldsm) done
#pragma unroll
        for (int j = 0; j < 4; j++) {
            int cu = ldc + j;
            size_t go = (size_t)(kt + ldrow) * Hd + cu * 8;
            *(uint4*)&sKh[ldrow][cu * 8] = *(const uint4*)(kh_g + go);
            *(uint4*)&sKl[ldrow][cu * 8] = *(const uint4*)(kl_g + go);
            *(uint4*)&sVh[ldrow][cu * 8] = *(const uint4*)(vh_g + go);
            *(uint4*)&sVl[ldrow][cu * 8] = *(const uint4*)(vl_g + go);
        }
        __syncthreads();

        // ---- QK: scores c[8][4] ----
        float c[8][4];
#pragma unroll
        for (int nt = 0; nt < 8; nt++)
#pragma unroll
            for (int r = 0; r < 4; r++) c[nt][r] = 0.0f;

        uint32_t bfr[8][2];
#pragma unroll
        for (int ks = 0; ks < 4; ks++) {
#pragma unroll
            for (int m = 0; m < 4; m++) {
                uint32_t t4[4];
                ldsm_x4(t4, khb + (uint32_t)(m * 16 + kRow) * 144 + kCol + ks * 32);
                bfr[2 * m][0] = t4[0]; bfr[2 * m][1] = t4[1];
                bfr[2 * m + 1][0] = t4[2]; bfr[2 * m + 1][1] = t4[3];
            }
#pragma unroll
            for (int nt = 0; nt < 8; nt++) mma16816(c[nt], qh[ks], bfr[nt]);
#pragma unroll
            for (int nt = 0; nt < 8; nt++) mma16816(c[nt], ql[ks], bfr[nt]);
#pragma unroll
            for (int m = 0; m < 4; m++) {
                uint32_t t4[4];
                ldsm_x4(t4, klb + (uint32_t)(m * 16 + kRow) * 144 + kCol + ks * 32);
                bfr[2 * m][0] = t4[0]; bfr[2 * m][1] = t4[1];
                bfr[2 * m + 1][0] = t4[2]; bfr[2 * m + 1][1] = t4[3];
            }
#pragma unroll
            for (int nt = 0; nt < 8; nt++) mma16816(c[nt], qh[ks], bfr[nt]);
        }

        // ---- bias ----
        const int jb = kt + 63 - rg + tg * 2;
#pragma unroll
        for (int nt = 0; nt < 8; nt++) {
            int j0 = jb + nt * 8;
            c[nt][0] += biasf[j0];
            c[nt][1] += biasf[j0 + 1];
            c[nt][2] += biasf[j0 - 8];
            c[nt][3] += biasf[j0 - 7];
        }

        // ---- online softmax (rows rg, rg+8; quad lanes share a row) ----
        float m0 = c[0][0], m1 = c[0][2];
#pragma unroll
        for (int nt = 0; nt < 8; nt++) {
            m0 = fmaxf(m0, fmaxf(c[nt][0], c[nt][1]));
            m1 = fmaxf(m1, fmaxf(c[nt][2], c[nt][3]));
        }
        m0 = fmaxf(m0, __shfl_xor_sync(0xffffffffu, m0, 1));
        m0 = fmaxf(m0, __shfl_xor_sync(0xffffffffu, m0, 2));
        m1 = fmaxf(m1, __shfl_xor_sync(0xffffffffu, m1, 1));
        m1 = fmaxf(m1, __shfl_xor_sync(0xffffffffu, m1, 2));
        float mn0 = fmaxf(mrun0, m0), mn1 = fmaxf(mrun1, m1);
        float sc0 = __expf(mrun0 - mn0), sc1 = __expf(mrun1 - mn1);
        mrun0 = mn0; mrun1 = mn1;
        lr0 *= sc0; lr1 *= sc1;
#pragma unroll
        for (int nt = 0; nt < 8; nt++) {
            onn[nt][0] *= sc0; onn[nt][1] *= sc0;
            onn[nt][2] *= sc1; onn[nt][3] *= sc1;
        }
#pragma unroll
        for (int nt = 0; nt < 8; nt++) {
            c[nt][0] = __expf(c[nt][0] - mn0);
            c[nt][1] = __expf(c[nt][1] - mn0);
            c[nt][2] = __expf(c[nt][2] - mn1);
            c[nt][3] = __expf(c[nt][3] - mn1);
            lr0 += c[nt][0] + c[nt][1];
            lr1 += c[nt][2] + c[nt][3];
        }

        // ---- P fragments (hi/lo) from score frags ----
        uint32_t ph[4][4], pl[4][4];
#pragma unroll
        for (int ks = 0; ks < 4; ks++) {
            const float* ce = c[2 * ks];
            const float* co = c[2 * ks + 1];
            __nv_bfloat162 h0 = __floats2bfloat162_rn(ce[0], ce[1]);
            __nv_bfloat162 h1 = __floats2bfloat162_rn(ce[2], ce[3]);
            __nv_bfloat162 h2 = __floats2bfloat162_rn(co[0], co[1]);
            __nv_bfloat162 h3 = __floats2bfloat162_rn(co[2], co[3]);
            ph[ks][0] = *(uint32_t*)&h0; ph[ks][1] = *(uint32_t*)&h1;
            ph[ks][2] = *(uint32_t*)&h2; ph[ks][3] = *(uint32_t*)&h3;
            pl[ks][0] = pack_bf2(ce[0] - __bfloat162float(h0.x), ce[1] - __bfloat162float(h0.y));
            pl[ks][1] = pack_bf2(ce[2] - __bfloat162float(h1.x), ce[3] - __bfloat162float(h1.y));
            pl[ks][2] = pack_bf2(co[0] - __bfloat162float(h2.x), co[1] - __bfloat162float(h2.y));
            pl[ks][3] = pack_bf2(co[2] - __bfloat162float(h3.x), co[3] - __bfloat162float(h3.y));
        }

        // ---- PV: O += Ph.Vh + Pl.Vh + Ph.Vl ----
#pragma unroll
        for (int ks = 0; ks < 4; ks++) {
#pragma unroll
            for (int n2 = 0; n2 < 4; n2++) {
                uint32_t t4[4];
                ldsm_x4_t(t4, vhb + (uint32_t)(ks * 16 + vRow) * 144 + (uint32_t)(n2 * 16) * 2 + vCol);
                bfr[2 * n2][0] = t4[0]; bfr[2 * n2][1] = t4[1];
                bfr[2 * n2 + 1][0] = t4[2]; bfr[2 * n2 + 1][1] = t4[3];
            }
#pragma unroll
            for (int nt = 0; nt < 8; nt++) mma16816(onn[nt], ph[ks], bfr[nt]);
#pragma unroll
            for (int nt = 0; nt < 8; nt++) mma16816(onn[nt], pl[ks], bfr[nt]);
#pragma unroll
            for (int n2 = 0; n2 < 4; n2++) {
                uint32_t t4[4];
                ldsm_x4_t(t4, vlb + (uint32_t)(ks * 16 + vRow) * 144 + (uint32_t)(n2 * 16) * 2 + vCol);
                bfr[2 * n2][0] = t4[0]; bfr[2 * n2][1] = t4[1];
                bfr[2 * n2 + 1][0] = t4[2]; bfr[2 * n2 + 1][1] = t4[3];
            }
#pragma unroll
            for (int nt = 0; nt < 8; nt++) mma16816(onn[nt], ph[ks], bfr[nt]);
        }
    }

    // ---- finalize: full row sums, normalize, write hi/lo output ----
    lr0 += __shfl_xor_sync(0xffffffffu, lr0, 1);
    lr0 += __shfl_xor_sync(0xffffffffu, lr0, 2);
    lr1 += __shfl_xor_sync(0xffffffffu, lr1, 1);
    lr1 += __shfl_xor_sync(0xffffffffu, lr1, 2);
    float inv0 = 1.0f / lr0, inv1 = 1.0f / lr1;

    const size_t s0 = (size_t)q0 + rg;
    __nv_bfloat16* oh0 = g_ah + ((size_t)b * Sq + s0) * Dm + h * Hd;
    __nv_bfloat16* ol0 = g_al + ((size_t)b * Sq + s0) * Dm + h * Hd;
#pragma unroll
    for (int nt = 0; nt < 8; nt++) {
        int d = nt * 8 + tg * 2;
        float a0 = onn[nt][0] * inv0, a1 = onn[nt][1] * inv0;
        float b0 = onn[nt][2] * inv1, b1 = onn[nt][3] * inv1;
        __nv_bfloat162 h0 = __floats2bfloat162_rn(a0, a1);
        __nv_bfloat162 h1 = __floats2bfloat162_rn(b0, b1);
        *(__nv_bfloat162*)(oh0 + d) = h0;
        *(__nv_bfloat162*)(oh0 + 8 * Dm + d) = h1;
        __nv_bfloat162 l0 = __floats2bfloat162_rn(a0 - __bfloat162float(h0.x),
                                                  a1 - __bfloat162float(h0.y));
        __nv_bfloat162 l1 = __floats2bfloat162_rn(b0 - __bfloat162float(h1.x),
                                                  b1 - __bfloat162float(h1.y));
        *(__nv_bfloat162*)(ol0 + d) = l0;
        *(__nv_bfloat162*)(ol0 + 8 * Dm + d) = l1;
    }
}

// ---------------- launch -----------------------------------------------------
extern "C" void kernel_launch(void* const* d_in, const int* in_sizes, int n_in,
                              void* d_out, int out_size) {
    (void)in_sizes; (void)n_in; (void)out_size;
    const float* x  = (const float*)d_in[0];
    const float* wq = (const float*)d_in[1];
    const float* wk = (const float*)d_in[2];
    const float* wv = (const float*)d_in[3];
    const float* wo = (const float*)d_in[4];
    const float* rb = (const float*)d_in[5];
    float* out = (float*)d_out;

    // 1. bucket LUT + past_bias -> second output region [1,H,S,S]
    lut_kernel<<<16, 256>>>();
    bias_kernel<<<dim3(Sq, Hn), 512>>>(rb, out + (size_t)Bb * Sq * Dm);

    // 2. split x and weights into bf16 hi/lo
    split_kernel<<<4096, 256>>>(x, 0, Bb * Sq * Dm / 4);
    split_kernel<<<1024, 256>>>(wq, 1, MM / 4);
    split_kernel<<<1024, 256>>>(wk, 2, MM / 4);
    split_kernel<<<1024, 256>>>(wv, 3, MM / 4);
    split_kernel<<<1024, 256>>>(wo, 4, MM / 4);

    // 3. Q/K/V projections -> bf16 hi/lo [B,H,S,d] (Q fused with 1/8 scale)
    dim3 gg(Dm / 128, (Bb * Sq) / 128);   // (8, 32)
    gemm_mma<<<gg, 256>>>(nullptr, 0, 0, 0.125f);
    gemm_mma<<<gg, 256>>>(nullptr, 1, 1, 1.0f);
    gemm_mma<<<gg, 256>>>(nullptr, 2, 2, 1.0f);

    // 4. flash attention (mma.sync) -> g_ah/g_al [B,S,H*d] hi/lo
    attn_mma<<<dim3(Sq / 64, Hn, Bb), 128>>>(rb);

    // 5. output projection -> first output region [B,S,D] fp32
    gemm_mma<<<gg, 256>>>(out, 3, 3, 1.0f);
}

// round 11
// speedup vs baseline: 2.6988x; 1.1056x over previous
#include <cuda_runtime.h>
#include <cuda_bf16.h>
#include <math.h>
#include <stdint.h>

// Problem constants
#define Bb 2
#define Sq 2048
#define Dm 1024
#define Hn 16
#define Hd 64
#define MM (Dm * Dm)

// ---------------- scratch (static device globals: no allocation allowed) ----
__device__ unsigned char g_bucket[4096];      // bucket LUT for rp+2047
__device__ __nv_bfloat16 g_ah[Bb * Sq * Dm];  // activation hi (x, later attn out)
__device__ __nv_bfloat16 g_al[Bb * Sq * Dm];  // activation lo
__device__ __nv_bfloat16 g_wh[4 * MM];        // weights hi (q,k,v,o)
__device__ __nv_bfloat16 g_wl[4 * MM];        // weights lo
__device__ __nv_bfloat16 g_qh[Bb * Hn * Sq * Hd];  // Q hi [B,H,S,d], pre-scaled 1/8
__device__ __nv_bfloat16 g_ql[Bb * Hn * Sq * Hd];
__device__ __nv_bfloat16 g_kh[Bb * Hn * Sq * Hd];
__device__ __nv_bfloat16 g_kl[Bb * Hn * Sq * Hd];
__device__ __nv_bfloat16 g_vh[Bb * Hn * Sq * Hd];
__device__ __nv_bfloat16 g_vl[Bb * Hn * Sq * Hd];

// ================= PTX helpers (sm_80+ baseline, valid on plain sm_103) =====
__device__ __forceinline__ uint32_t smem_u32(const void* p) {
    uint32_t a;
    asm("{ .reg .u64 t; cvta.to.shared.u64 t, %1; cvt.u32.u64 %0, t; }" : "=r"(a) : "l"(p));
    return a;
}
__device__ __forceinline__ void ldsm_x4(uint32_t r[4], uint32_t addr) {
    asm volatile("ldmatrix.sync.aligned.m8n8.x4.shared.b16 {%0,%1,%2,%3}, [%4];"
                 : "=r"(r[0]), "=r"(r[1]), "=r"(r[2]), "=r"(r[3]) : "r"(addr));
}
__device__ __forceinline__ void ldsm_x4_t(uint32_t r[4], uint32_t addr) {
    asm volatile("ldmatrix.sync.aligned.m8n8.x4.trans.shared.b16 {%0,%1,%2,%3}, [%4];"
                 : "=r"(r[0]), "=r"(r[1]), "=r"(r[2]), "=r"(r[3]) : "r"(addr));
}
__device__ __forceinline__ void mma16816(float c[4], const uint32_t a[4], const uint32_t b[2]) {
    asm volatile(
        "mma.sync.aligned.m16n8k16.row.col.f32.bf16.bf16.f32 "
        "{%0,%1,%2,%3}, {%4,%5,%6,%7}, {%8,%9}, {%0,%1,%2,%3};"
        : "+f"(c[0]), "+f"(c[1]), "+f"(c[2]), "+f"(c[3])
        : "r"(a[0]), "r"(a[1]), "r"(a[2]), "r"(a[3]), "r"(b[0]), "r"(b[1]));
}
__device__ __forceinline__ void cpasync16(uint32_t s, const void* g) {
    asm volatile("cp.async.cg.shared.global [%0], [%1], 16;" :: "r"(s), "l"(g));
}
__device__ __forceinline__ void cp_commit() { asm volatile("cp.async.commit_group;"); }
__device__ __forceinline__ void cp_wait0() { asm volatile("cp.async.wait_group 0;"); }
__device__ __forceinline__ void cp_wait1() { asm volatile("cp.async.wait_group 1;"); }
__device__ __forceinline__ void cp_wait2() { asm volatile("cp.async.wait_group 2;"); }
__device__ __forceinline__ uint32_t pack_bf2(float a, float b) {
    __nv_bfloat162 t = __floats2bfloat162_rn(a, b);
    return *(uint32_t*)&t;
}

// ---------------- T5 relative position bucket ------------------------------
__device__ __forceinline__ int rel_bucket(int rp) {
    int ret = (rp >= 0) ? 16 : 0;
    int n = rp < 0 ? -rp : rp;
    if (n < 8) return ret + n;
    float v = logf((float)n * 0.125f) / logf(16.0f) * 8.0f;
    int vi = 8 + (int)v;
    if (vi > 15) vi = 15;
    return ret + vi;
}

__global__ void lut_kernel() {
    int i = blockIdx.x * 256 + threadIdx.x;
    if (i < 4096) g_bucket[i] = (unsigned char)rel_bucket(i - 2047);
}

__global__ void bias_kernel(const float* __restrict__ relb, float* __restrict__ out) {
    int q = blockIdx.x;
    int h = blockIdx.y;
    int k0 = threadIdx.x * 4;
    int lb = k0 - q + 2047;
    float4 v;
    v.x = relb[(int)g_bucket[lb + 0] * Hn + h];
    v.y = relb[(int)g_bucket[lb + 1] * Hn + h];
    v.z = relb[(int)g_bucket[lb + 2] * Hn + h];
    v.w = relb[(int)g_bucket[lb + 3] * Hn + h];
    *(float4*)(out + ((size_t)h * Sq + q) * Sq + k0) = v;
}

// ---------------- fused fp32 -> bf16 hi/lo split (x + 4 weights) ------------
__global__ void splitall_kernel(const float* __restrict__ x,
                                const float* __restrict__ wq, const float* __restrict__ wk,
                                const float* __restrict__ wv, const float* __restrict__ wo) {
    int i = blockIdx.x * 256 + threadIdx.x;     // 0 .. 2097151 float4 slots
    const float* src;
    __nv_bfloat16 *hi, *lo;
    int idx;
    if (i < 1048576) {                          // x: Bb*Sq*Dm/4
        src = x; idx = i; hi = g_ah; lo = g_al;
    } else {
        int j = i - 1048576;
        int w = j >> 18;                        // MM/4 = 262144 per weight
        idx = j & 262143;
        src = (w == 0) ? wq : (w == 1) ? wk : (w == 2) ? wv : wo;
        hi = g_wh + (size_t)w * MM;
        lo = g_wl + (size_t)w * MM;
    }
    float4 v = ((const float4*)src)[idx];
    float f[4] = {v.x, v.y, v.z, v.w};
    __nv_bfloat16 h[4], l[4];
#pragma unroll
    for (int j = 0; j < 4; j++) {
        h[j] = __float2bfloat16(f[j]);
        l[j] = __float2bfloat16(f[j] - __bfloat162float(h[j]));
    }
    ((__nv_bfloat162*)hi)[idx * 2 + 0] = __nv_bfloat162(h[0], h[1]);
    ((__nv_bfloat162*)hi)[idx * 2 + 1] = __nv_bfloat162(h[2], h[3]);
    ((__nv_bfloat162*)lo)[idx * 2 + 0] = __nv_bfloat162(l[0], l[1]);
    ((__nv_bfloat162*)lo)[idx * 2 + 1] = __nv_bfloat162(l[2], l[3]);
}

// ---------------- warp-MMA GEMM, per-chunk 3-leg split-bf16 ------------------
// C[M,N] = A[M,K] @ W[N,K]^T; per k16 chunk: load Ah,Al,Wh,Wl tiles, compute
// Ah.Wh + Al.Wh + Ah.Wl into one fp32 accumulator. 64 chunks, 3-stage cp.async.
// Block tile 128x128, 256 threads (8 warps 4Mx2N). Smem row 48B conflict-free.
// csel: 0/1/2 -> q/k/v hi+lo bf16 scatter [B,H,S,d]; 3 -> fp32 row-major Cext.
#define GSTR 48        // smem row stride bytes
#define GARR 6144      // bytes per tile (128*48)
#define GSTG 24576     // bytes per stage (4 tiles)
#define NCHUNK 64

__global__ __launch_bounds__(256, 2)
void gemm_mma(float* __restrict__ Cext, int wsel, int csel, float scale) {
    __shared__ __nv_bfloat16 S[3][4][128][24];   // [stage][Ah,Al,Wh,Wl][row][col]

    const int tid = threadIdx.x;
    const int lane = tid & 31, warp = tid >> 5;
    const int wm = warp & 3, wn = warp >> 2;
    const int bx = blockIdx.x, by = blockIdx.y;   // (N/128=8, M/128=32)

    const __nv_bfloat16* wh = g_wh + (size_t)wsel * MM;
    const __nv_bfloat16* wl = g_wl + (size_t)wsel * MM;
    const size_t aoff = (size_t)by * 128 * 1024;
    const size_t woff = (size_t)bx * 128 * 1024;

    const int ldrow = tid >> 1;           // 0..127
    const int ldh = (tid & 1);            // 16B half of the 32B k16 row

    const uint32_t sb = smem_u32(&S[0][0][0][0]);
    const int arow = wm * 32 + (lane & 15);
    const int acol = ((lane >> 4) & 1) * 16;
    const int brow = wn * 64 + ((lane >> 4) & 1) * 8 + (lane & 7);
    const int bcol = ((lane >> 3) & 1) * 16;

    float c[2][8][4];
#pragma unroll
    for (int mt = 0; mt < 2; mt++)
#pragma unroll
        for (int nt = 0; nt < 8; nt++)
#pragma unroll
            for (int r = 0; r < 4; r++) c[mt][nt][r] = 0.0f;

#define ISSUE(CH) do {                                                           \
    int _st = (CH) % 3;                                                          \
    size_t _go = (size_t)ldrow * 1024 + (CH) * 16 + ldh * 8;                     \
    uint32_t _so = sb + _st * GSTG + ldrow * GSTR + ldh * 16;                    \
    cpasync16(_so,            g_ah + aoff + _go);                                \
    cpasync16(_so + GARR,     g_al + aoff + _go);                                \
    cpasync16(_so + 2 * GARR, wh + woff + _go);                                  \
    cpasync16(_so + 3 * GARR, wl + woff + _go);                                  \
    cp_commit();                                                                 \
} while (0)

    ISSUE(0); ISSUE(1); ISSUE(2);

    for (int it = 0; it < NCHUNK; it++) {
        if (it < NCHUNK - 2)       cp_wait2();
        else if (it == NCHUNK - 2) cp_wait1();
        else                       cp_wait0();
        __syncthreads();

        const uint32_t base = sb + (it % 3) * GSTG;
        uint32_t a4[2][4], b4[8][2];
        // Wh fragments
#pragma unroll
        for (int nt2 = 0; nt2 < 4; nt2++) {
            uint32_t r[4];
            ldsm_x4(r, base + 2 * GARR + (uint32_t)(brow + nt2 * 16) * GSTR + bcol);
            b4[nt2 * 2][0] = r[0]; b4[nt2 * 2][1] = r[1];
            b4[nt2 * 2 + 1][0] = r[2]; b4[nt2 * 2 + 1][1] = r[3];
        }
        // leg 1: Ah . Wh
#pragma unroll
        for (int mt = 0; mt < 2; mt++)
            ldsm_x4(a4[mt], base + (uint32_t)(arow + mt * 16) * GSTR + acol);
#pragma unroll
        for (int mt = 0; mt < 2; mt++)
#pragma unroll
            for (int nt = 0; nt < 8; nt++) mma16816(c[mt][nt], a4[mt], b4[nt]);
        // leg 2: Al . Wh
#pragma unroll
        for (int mt = 0; mt < 2; mt++)
            ldsm_x4(a4[mt], base + GARR + (uint32_t)(arow + mt * 16) * GSTR + acol);
#pragma unroll
        for (int mt = 0; mt < 2; mt++)
#pragma unroll
            for (int nt = 0; nt < 8; nt++) mma16816(c[mt][nt], a4[mt], b4[nt]);
        // leg 3: Ah . Wl
#pragma unroll
        for (int nt2 = 0; nt2 < 4; nt2++) {
            uint32_t r[4];
            ldsm_x4(r, base + 3 * GARR + (uint32_t)(brow + nt2 * 16) * GSTR + bcol);
            b4[nt2 * 2][0] = r[0]; b4[nt2 * 2][1] = r[1];
            b4[nt2 * 2 + 1][0] = r[2]; b4[nt2 * 2 + 1][1] = r[3];
        }
#pragma unroll
        for (int mt = 0; mt < 2; mt++)
            ldsm_x4(a4[mt], base + (uint32_t)(arow + mt * 16) * GSTR + acol);
#pragma unroll
        for (int mt = 0; mt < 2; mt++)
#pragma unroll
            for (int nt = 0; nt < 8; nt++) mma16816(c[mt][nt], a4[mt], b4[nt]);

        __syncthreads();
        if (it + 3 < NCHUNK) ISSUE(it + 3);
    }
#undef ISSUE

    // epilogue
    const int g = lane >> 2, tg = lane & 3;
#pragma unroll
    for (int mt = 0; mt < 2; mt++) {
#pragma unroll
        for (int nt = 0; nt < 8; nt++) {
            int m = by * 128 + wm * 32 + mt * 16 + g;
            int n = bx * 128 + wn * 64 + nt * 8 + tg * 2;
            float v00 = c[mt][nt][0] * scale, v01 = c[mt][nt][1] * scale;
            float v10 = c[mt][nt][2] * scale, v11 = c[mt][nt][3] * scale;
            if (csel == 3) {
                *(float2*)(Cext + (size_t)m * 1024 + n) = make_float2(v00, v01);
                *(float2*)(Cext + (size_t)(m + 8) * 1024 + n) = make_float2(v10, v11);
            } else {
                __nv_bfloat16* Chi = (csel == 0) ? g_qh : (csel == 1 ? g_kh : g_vh);
                __nv_bfloat16* Clo = (csel == 0) ? g_ql : (csel == 1 ? g_kl : g_vl);
                int head = n >> 6, d = n & 63;
                int bbi = m >> 11, ssi = m & 2047;
                size_t base2 = (((size_t)bbi * Hn + head) * Sq + ssi) * Hd + d;
                __nv_bfloat162 h0 = __floats2bfloat162_rn(v00, v01);
                __nv_bfloat162 h1 = __floats2bfloat162_rn(v10, v11);
                __nv_bfloat162 l0 = __floats2bfloat162_rn(
                    v00 - __bfloat162float(h0.x), v01 - __bfloat162float(h0.y));
                __nv_bfloat162 l1 = __floats2bfloat162_rn(
                    v10 - __bfloat162float(h1.x), v11 - __bfloat162float(h1.y));
                *(__nv_bfloat162*)(Chi + base2) = h0;
                *(__nv_bfloat162*)(Chi + base2 + 8 * Hd) = h1;
                *(__nv_bfloat162*)(Clo + base2) = l0;
                *(__nv_bfloat162*)(Clo + base2 + 8 * Hd) = l1;
            }
        }
    }
}

// ---------------- flash attention via mma.sync + cp.async prefetch -----------
// Block: 128 thr = 4 warps, 64 queries. K-tile 64. Single-buffered K/V tiles;
// K(i+1) prefetched during softmax+PV, V(i+1) during next QK (FIFO groups).
__global__ __launch_bounds__(128, 3)
void attn_mma(const float* __restrict__ relb) {
    __shared__ __nv_bfloat16 sKh[64][72];
    __shared__ __nv_bfloat16 sKl[64][72];
    __shared__ __nv_bfloat16 sVh[64][72];
    __shared__ __nv_bfloat16 sVl[64][72];
    __shared__ float biasf[2112];

    const int tid = threadIdx.x;
    const int lane = tid & 31, warp = tid >> 5;
    const int g = lane >> 2, tg = lane & 3;
    const int h = blockIdx.y, b = blockIdx.z;
    const int q0 = blockIdx.x * 64;

    const size_t bh = ((size_t)b * Hn + h) * Sq;
    const int ldrow = tid >> 1;           // 0..63
    const int ldc = (tid & 1) * 4;        // uint4 index base (of 8 per row)

    const uint32_t khb = smem_u32(&sKh[0][0]);
    const uint32_t klb = smem_u32(&sKl[0][0]);
    const uint32_t vhb = smem_u32(&sVh[0][0]);
    const uint32_t vlb = smem_u32(&sVl[0][0]);

    const __nv_bfloat16* kh_g = g_kh + bh * Hd;
    const __nv_bfloat16* kl_g = g_kl + bh * Hd;
    const __nv_bfloat16* vh_g = g_vh + bh * Hd;
    const __nv_bfloat16* vl_g = g_vl + bh * Hd;

#define ISSK(KT) do {                                                            \
    size_t _go = (size_t)((KT) + ldrow) * Hd;                                    \
    uint32_t _so = ldrow * 144;                                                  \
    _Pragma("unroll")                                                            \
    for (int _j = 0; _j < 4; _j++) {                                             \
        int _cu = ldc + _j;                                                      \
        cpasync16(khb + _so + _cu * 16, kh_g + _go + _cu * 8);                   \
        cpasync16(klb + _so + _cu * 16, kl_g + _go + _cu * 8);                   \
    }                                                                            \
    cp_commit();                                                                 \
} while (0)

#define ISSV(KT) do {                                                            \
    size_t _go = (size_t)((KT) + ldrow) * Hd;                                    \
    uint32_t _so = ldrow * 144;                                                  \
    _Pragma("unroll")                                                            \
    for (int _j = 0; _j < 4; _j++) {                                             \
        int _cu = ldc + _j;                                                      \
        cpasync16(vhb + _so + _cu * 16, vh_g + _go + _cu * 8);                   \
        cpasync16(vlb + _so + _cu * 16, vl_g + _go + _cu * 8);                   \
    }                                                                            \
    cp_commit();                                                                 \
} while (0)

    // K0 streaming while Q stages through the V buffers
    ISSK(0);
    {
        const __nv_bfloat16* qh_g = g_qh + (bh + q0) * Hd;
        const __nv_bfloat16* ql_g = g_ql + (bh + q0) * Hd;
#pragma unroll
        for (int j = 0; j < 4; j++) {
            int cu = ldc + j;
            *(uint4*)&sVh[ldrow][cu * 8] = *(const uint4*)(qh_g + (size_t)ldrow * Hd + cu * 8);
            *(uint4*)&sVl[ldrow][cu * 8] = *(const uint4*)(ql_g + (size_t)ldrow * Hd + cu * 8);
        }
    }
    // bias table: biasf[j] = bias(key - q) where j = key + 63 - (q - q0)
    for (int j = tid; j < 2112; j += 128)
        biasf[j] = relb[(int)g_bucket[j + 1984 - q0] * Hn + h];
    __syncthreads();

    uint32_t qh[4][4], ql[4][4];
    {
        const uint32_t aoff = (uint32_t)(warp * 16 + (lane & 15)) * 144 + ((lane >> 4) & 1) * 16;
#pragma unroll
        for (int ks = 0; ks < 4; ks++) {
            ldsm_x4(qh[ks], vhb + aoff + ks * 32);
            ldsm_x4(ql[ks], vlb + aoff + ks * 32);
        }
    }
    __syncthreads();
    ISSV(0);                               // pending groups: {K0, V0}

    float onn[8][4];
#pragma unroll
    for (int nt = 0; nt < 8; nt++)
#pragma unroll
        for (int r = 0; r < 4; r++) onn[nt][r] = 0.0f;
    float mrun0 = -1e30f, mrun1 = -1e30f, lr0 = 0.0f, lr1 = 0.0f;

    const int rg = warp * 16 + g;                      // block-local row (first)
    const uint32_t kRow = ((lane >> 4) & 1) * 8 + (lane & 7);
    const uint32_t kCol = ((lane >> 3) & 1) * 16;
    const uint32_t vRow = ((lane >> 3) & 1) * 8 + (lane & 7);
    const uint32_t vCol = (uint32_t)((lane >> 4) * 8) * 2;

    for (int ti = 0; ti < 32; ti++) {
        const int kt = ti * 64;
        cp_wait1();                        // K(ti) retired (FIFO)
        __syncthreads();

        // ---- QK: scores c[8][4] ----
        float c[8][4];
#pragma unroll
        for (int nt = 0; nt < 8; nt++)
#pragma unroll
            for (int r = 0; r < 4; r++) c[nt][r] = 0.0f;

        uint32_t bfr[8][2];
#pragma unroll
        for (int ks = 0; ks < 4; ks++) {
#pragma unroll
            for (int m = 0; m < 4; m++) {
                uint32_t t4[4];
                ldsm_x4(t4, khb + (uint32_t)(m * 16 + kRow) * 144 + kCol + ks * 32);
                bfr[2 * m][0] = t4[0]; bfr[2 * m][1] = t4[1];
                bfr[2 * m + 1][0] = t4[2]; bfr[2 * m + 1][1] = t4[3];
            }
#pragma unroll
            for (int nt = 0; nt < 8; nt++) mma16816(c[nt], qh[ks], bfr[nt]);
#pragma unroll
            for (int nt = 0; nt < 8; nt++) mma16816(c[nt], ql[ks], bfr[nt]);
#pragma unroll
            for (int m = 0; m < 4; m++) {
                uint32_t t4[4];
                ldsm_x4(t4, klb + (uint32_t)(m * 16 + kRow) * 144 + kCol + ks * 32);
                bfr[2 * m][0] = t4[0]; bfr[2 * m][1] = t4[1];
                bfr[2 * m + 1][0] = t4[2]; bfr[2 * m + 1][1] = t4[3];
            }
#pragma unroll
            for (int nt = 0; nt < 8; nt++) mma16816(c[nt], qh[ks], bfr[nt]);
        }
        __syncthreads();                   // all warps done reading K tiles
        if (ti < 31) ISSK(kt + 64);        // prefetch next K during softmax+PV

        // ---- bias ----
        const int jb = kt + 63 - rg + tg * 2;
#pragma unroll
        for (int nt = 0; nt < 8; nt++) {
            int j0 = jb + nt * 8;
            c[nt][0] += biasf[j0];
            c[nt][1] += biasf[j0 + 1];
            c[nt][2] += biasf[j0 - 8];
            c[nt][3] += biasf[j0 - 7];
        }

        // ---- online softmax (rows rg, rg+8; quad lanes share a row) ----
        float m0 = c[0][0], m1 = c[0][2];
#pragma unroll
        for (int nt = 0; nt < 8; nt++) {
            m0 = fmaxf(m0, fmaxf(c[nt][0], c[nt][1]));
            m1 = fmaxf(m1, fmaxf(c[nt][2], c[nt][3]));
        }
        m0 = fmaxf(m0, __shfl_xor_sync(0xffffffffu, m0, 1));
        m0 = fmaxf(m0, __shfl_xor_sync(0xffffffffu, m0, 2));
        m1 = fmaxf(m1, __shfl_xor_sync(0xffffffffu, m1, 1));
        m1 = fmaxf(m1, __shfl_xor_sync(0xffffffffu, m1, 2));
        float mn0 = fmaxf(mrun0, m0), mn1 = fmaxf(mrun1, m1);
        float sc0 = __expf(mrun0 - mn0), sc1 = __expf(mrun1 - mn1);
        mrun0 = mn0; mrun1 = mn1;
        lr0 *= sc0; lr1 *= sc1;
#pragma unroll
        for (int nt = 0; nt < 8; nt++) {
            onn[nt][0] *= sc0; onn[nt][1] *= sc0;
            onn[nt][2] *= sc1; onn[nt][3] *= sc1;
        }
#pragma unroll
        for (int nt = 0; nt < 8; nt++) {
            c[nt][0] = __expf(c[nt][0] - mn0);
            c[nt][1] = __expf(c[nt][1] - mn0);
            c[nt][2] = __expf(c[nt][2] - mn1);
            c[nt][3] = __expf(c[nt][3] - mn1);
            lr0 += c[nt][0] + c[nt][1];
            lr1 += c[nt][2] + c[nt][3];
        }

        // ---- P fragments (hi/lo) from score frags ----
        uint32_t ph[4][4], pl[4][4];
#pragma unroll
        for (int ks = 0; ks < 4; ks++) {
            const float* ce = c[2 * ks];
            const float* co = c[2 * ks + 1];
            __nv_bfloat162 h0 = __floats2bfloat162_rn(ce[0], ce[1]);
            __nv_bfloat162 h1 = __floats2bfloat162_rn(ce[2], ce[3]);
            __nv_bfloat162 h2 = __floats2bfloat162_rn(co[0], co[1]);
            __nv_bfloat162 h3 = __floats2bfloat162_rn(co[2], co[3]);
            ph[ks][0] = *(uint32_t*)&h0; ph[ks][1] = *(uint32_t*)&h1;
            ph[ks][2] = *(uint32_t*)&h2; ph[ks][3] = *(uint32_t*)&h3;
            pl[ks][0] = pack_bf2(ce[0] - __bfloat162float(h0.x), ce[1] - __bfloat162float(h0.y));
            pl[ks][1] = pack_bf2(ce[2] - __bfloat162float(h1.x), ce[3] - __bfloat162float(h1.y));
            pl[ks][2] = pack_bf2(co[0] - __bfloat162float(h2.x), co[1] - __bfloat162float(h2.y));
            pl[ks][3] = pack_bf2(co[2] - __bfloat162float(h3.x), co[3] - __bfloat162float(h3.y));
        }

        // V(ti) readiness: after the K(ti+1) commit, FIFO pending = {V(ti), K(ti+1)}
        if (ti < 31) cp_wait1(); else cp_wait0();
        __syncthreads();

        // ---- PV: O += Ph.Vh + Pl.Vh + Ph.Vl ----
#pragma unroll
        for (int ks = 0; ks < 4; ks++) {
#pragma unroll
            for (int n2 = 0; n2 < 4; n2++) {
                uint32_t t4[4];
                ldsm_x4_t(t4, vhb + (uint32_t)(ks * 16 + vRow) * 144 + (uint32_t)(n2 * 16) * 2 + vCol);
                bfr[2 * n2][0] = t4[0]; bfr[2 * n2][1] = t4[1];
                bfr[2 * n2 + 1][0] = t4[2]; bfr[2 * n2 + 1][1] = t4[3];
            }
#pragma unroll
            for (int nt = 0; nt < 8; nt++) mma16816(onn[nt], ph[ks], bfr[nt]);
#pragma unroll
            for (int nt = 0; nt < 8; nt++) mma16816(onn[nt], pl[ks], bfr[nt]);
#pragma unroll
            for (int n2 = 0; n2 < 4; n2++) {
                uint32_t t4[4];
                ldsm_x4_t(t4, vlb + (uint32_t)(ks * 16 + vRow) * 144 + (uint32_t)(n2 * 16) * 2 + vCol);
                bfr[2 * n2][0] = t4[0]; bfr[2 * n2][1] = t4[1];
                bfr[2 * n2 + 1][0] = t4[2]; bfr[2 * n2 + 1][1] = t4[3];
            }
#pragma unroll
            for (int nt = 0; nt < 8; nt++) mma16816(onn[nt], ph[ks], bfr[nt]);
        }
        __syncthreads();                   // all warps done reading V tiles
        if (ti < 31) ISSV(kt + 64);        // prefetch next V during next QK
    }
#undef ISSK
#undef ISSV

    // ---- finalize: full row sums, normalize, write hi/lo output ----
    lr0 += __shfl_xor_sync(0xffffffffu, lr0, 1);
    lr0 += __shfl_xor_sync(0xffffffffu, lr0, 2);
    lr1 += __shfl_xor_sync(0xffffffffu, lr1, 1);
    lr1 += __shfl_xor_sync(0xffffffffu, lr1, 2);
    float inv0 = 1.0f / lr0, inv1 = 1.0f / lr1;

    const size_t s0 = (size_t)q0 + rg;
    __nv_bfloat16* oh0 = g_ah + ((size_t)b * Sq + s0) * Dm + h * Hd;
    __nv_bfloat16* ol0 = g_al + ((size_t)b * Sq + s0) * Dm + h * Hd;
#pragma unroll
    for (int nt = 0; nt < 8; nt++) {
        int d = nt * 8 + tg * 2;
        float a0 = onn[nt][0] * inv0, a1 = onn[nt][1] * inv0;
        float b0 = onn[nt][2] * inv1, b1 = onn[nt][3] * inv1;
        __nv_bfloat162 h0 = __floats2bfloat162_rn(a0, a1);
        __nv_bfloat162 h1 = __floats2bfloat162_rn(b0, b1);
        *(__nv_bfloat162*)(oh0 + d) = h0;
        *(__nv_bfloat162*)(oh0 + 8 * Dm + d) = h1;
        __nv_bfloat162 l0 = __floats2bfloat162_rn(a0 - __bfloat162float(h0.x),
                                                  a1 - __bfloat162float(h0.y));
        __nv_bfloat162 l1 = __floats2bfloat162_rn(b0 - __bfloat162float(h1.x),
                                                  b1 - __bfloat162float(h1.y));
        *(__nv_bfloat162*)(ol0 + d) = l0;
        *(__nv_bfloat162*)(ol0 + 8 * Dm + d) = l1;
    }
}

// ---------------- launch -----------------------------------------------------
// Launch order puts attn_mma at slot 6 so ncu (-s 5 -c 1) profiles it.
extern "C" void kernel_launch(void* const* d_in, const int* in_sizes, int n_in,
                              void* d_out, int out_size) {
    (void)in_sizes; (void)n_in; (void)out_size;
    const float* x  = (const float*)d_in[0];
    const float* wq = (const float*)d_in[1];
    const float* wk = (const float*)d_in[2];
    const float* wv = (const float*)d_in[3];
    const float* wo = (const float*)d_in[4];
    const float* rb = (const float*)d_in[5];
    float* out = (float*)d_out;

    // 1. bucket LUT
    lut_kernel<<<16, 256>>>();
    // 2. fused split of x + all weights into bf16 hi/lo
    splitall_kernel<<<8192, 256>>>(x, wq, wk, wv, wo);
    // 3-5. Q/K/V projections -> bf16 hi/lo [B,H,S,d] (Q fused with 1/8 scale)
    dim3 gg(Dm / 128, (Bb * Sq) / 128);   // (8, 32)
    gemm_mma<<<gg, 256>>>(nullptr, 0, 0, 0.125f);
    gemm_mma<<<gg, 256>>>(nullptr, 1, 1, 1.0f);
    gemm_mma<<<gg, 256>>>(nullptr, 2, 2, 1.0f);
    // 6. flash attention (mma.sync) -> g_ah/g_al hi/lo   [ncu captures this]
    attn_mma<<<dim3(Sq / 64, Hn, Bb), 128>>>(rb);
    // 7. past_bias -> second output region [1,H,S,S]
    bias_kernel<<<dim3(Sq, Hn), 512>>>(rb, out + (size_t)Bb * Sq * Dm);
    // 8. output projection -> first output region [B,S,D] fp32
    gemm_mma<<<gg, 256>>>(out, 3, 3, 1.0f);
}

// round 12
// speedup vs baseline: 2.8144x; 1.0429x over previous
#include <cuda_runtime.h>
#include <cuda_bf16.h>
#include <math.h>
#include <stdint.h>

// Problem constants
#define Bb 2
#define Sq 2048
#define Dm 1024
#define Hn 16
#define Hd 64
#define MM (Dm * Dm)

// ---------------- scratch (static device globals: no allocation allowed) ----
__device__ unsigned char g_bucket[4096];      // bucket LUT for rp+2047
__device__ __nv_bfloat16 g_ah[Bb * Sq * Dm];  // activation hi (x, later attn out)
__device__ __nv_bfloat16 g_al[Bb * Sq * Dm];  // activation lo
__device__ __nv_bfloat16 g_wh[4 * MM];        // weights hi (q,k,v,o)
__device__ __nv_bfloat16 g_wl[4 * MM];        // weights lo
__device__ __nv_bfloat16 g_qh[Bb * Hn * Sq * Hd];  // Q hi [B,H,S,d], pre-scaled 1/8
__device__ __nv_bfloat16 g_ql[Bb * Hn * Sq * Hd];
__device__ __nv_bfloat16 g_kh[Bb * Hn * Sq * Hd];
__device__ __nv_bfloat16 g_kl[Bb * Hn * Sq * Hd];
__device__ __nv_bfloat16 g_vh[Bb * Hn * Sq * Hd];
__device__ __nv_bfloat16 g_vl[Bb * Hn * Sq * Hd];

// ================= PTX helpers (sm_80+ baseline, valid on plain sm_103) =====
__device__ __forceinline__ uint32_t smem_u32(const void* p) {
    uint32_t a;
    asm("{ .reg .u64 t; cvta.to.shared.u64 t, %1; cvt.u32.u64 %0, t; }" : "=r"(a) : "l"(p));
    return a;
}
__device__ __forceinline__ void ldsm_x4(uint32_t r[4], uint32_t addr) {
    asm volatile("ldmatrix.sync.aligned.m8n8.x4.shared.b16 {%0,%1,%2,%3}, [%4];"
                 : "=r"(r[0]), "=r"(r[1]), "=r"(r[2]), "=r"(r[3]) : "r"(addr));
}
__device__ __forceinline__ void ldsm_x4_t(uint32_t r[4], uint32_t addr) {
    asm volatile("ldmatrix.sync.aligned.m8n8.x4.trans.shared.b16 {%0,%1,%2,%3}, [%4];"
                 : "=r"(r[0]), "=r"(r[1]), "=r"(r[2]), "=r"(r[3]) : "r"(addr));
}
__device__ __forceinline__ void mma16816(float c[4], const uint32_t a[4], const uint32_t b[2]) {
    asm volatile(
        "mma.sync.aligned.m16n8k16.row.col.f32.bf16.bf16.f32 "
        "{%0,%1,%2,%3}, {%4,%5,%6,%7}, {%8,%9}, {%0,%1,%2,%3};"
        : "+f"(c[0]), "+f"(c[1]), "+f"(c[2]), "+f"(c[3])
        : "r"(a[0]), "r"(a[1]), "r"(a[2]), "r"(a[3]), "r"(b[0]), "r"(b[1]));
}
__device__ __forceinline__ void cpasync16(uint32_t s, const void* g) {
    asm volatile("cp.async.cg.shared.global [%0], [%1], 16;" :: "r"(s), "l"(g));
}
__device__ __forceinline__ void cp_commit() { asm volatile("cp.async.commit_group;"); }
__device__ __forceinline__ void cp_wait0() { asm volatile("cp.async.wait_group 0;"); }
__device__ __forceinline__ void cp_wait1() { asm volatile("cp.async.wait_group 1;"); }
__device__ __forceinline__ void cp_wait2() { asm volatile("cp.async.wait_group 2;"); }
__device__ __forceinline__ uint32_t pack_bf2(float a, float b) {
    __nv_bfloat162 t = __floats2bfloat162_rn(a, b);
    return *(uint32_t*)&t;
}

// ---------------- T5 relative position bucket ------------------------------
__device__ __forceinline__ int rel_bucket(int rp) {
    int ret = (rp >= 0) ? 16 : 0;
    int n = rp < 0 ? -rp : rp;
    if (n < 8) return ret + n;
    float v = logf((float)n * 0.125f) / logf(16.0f) * 8.0f;
    int vi = 8 + (int)v;
    if (vi > 15) vi = 15;
    return ret + vi;
}

__global__ void lut_kernel() {
    int i = blockIdx.x * 256 + threadIdx.x;
    if (i < 4096) g_bucket[i] = (unsigned char)rel_bucket(i - 2047);
}

__global__ void bias_kernel(const float* __restrict__ relb, float* __restrict__ out) {
    int q = blockIdx.x;
    int h = blockIdx.y;
    int k0 = threadIdx.x * 4;
    int lb = k0 - q + 2047;
    float4 v;
    v.x = relb[(int)g_bucket[lb + 0] * Hn + h];
    v.y = relb[(int)g_bucket[lb + 1] * Hn + h];
    v.z = relb[(int)g_bucket[lb + 2] * Hn + h];
    v.w = relb[(int)g_bucket[lb + 3] * Hn + h];
    *(float4*)(out + ((size_t)h * Sq + q) * Sq + k0) = v;
}

// ---------------- fused fp32 -> bf16 hi/lo split (x + 4 weights) ------------
__global__ void splitall_kernel(const float* __restrict__ x,
                                const float* __restrict__ wq, const float* __restrict__ wk,
                                const float* __restrict__ wv, const float* __restrict__ wo) {
    int i = blockIdx.x * 256 + threadIdx.x;     // 0 .. 2097151 float4 slots
    const float* src;
    __nv_bfloat16 *hi, *lo;
    int idx;
    if (i < 1048576) {                          // x: Bb*Sq*Dm/4
        src = x; idx = i; hi = g_ah; lo = g_al;
    } else {
        int j = i - 1048576;
        int w = j >> 18;                        // MM/4 = 262144 per weight
        idx = j & 262143;
        src = (w == 0) ? wq : (w == 1) ? wk : (w == 2) ? wv : wo;
        hi = g_wh + (size_t)w * MM;
        lo = g_wl + (size_t)w * MM;
    }
    float4 v = ((const float4*)src)[idx];
    float f[4] = {v.x, v.y, v.z, v.w};
    __nv_bfloat16 h[4], l[4];
#pragma unroll
    for (int j = 0; j < 4; j++) {
        h[j] = __float2bfloat16(f[j]);
        l[j] = __float2bfloat16(f[j] - __bfloat162float(h[j]));
    }
    ((__nv_bfloat162*)hi)[idx * 2 + 0] = __nv_bfloat162(h[0], h[1]);
    ((__nv_bfloat162*)hi)[idx * 2 + 1] = __nv_bfloat162(h[2], h[3]);
    ((__nv_bfloat162*)lo)[idx * 2 + 0] = __nv_bfloat162(l[0], l[1]);
    ((__nv_bfloat162*)lo)[idx * 2 + 1] = __nv_bfloat162(l[2], l[3]);
}

// ---------------- warp-MMA GEMM, 4-stage ring, one barrier per chunk ---------
// C[M,N] = A[M,K] @ W[N,K]^T; per k16 chunk: Ah.Wh + Al.Wh + Ah.Wl (Ah frags
// kept in regs across legs). 64 chunks, 4-stage cp.async ring with 3-ahead
// prefetch issued right after the single barrier.
// Dynamic smem: 4 stages x 4 tiles x 128 rows x 48B = 98304 bytes.
#define GSTR 48        // smem row stride bytes
#define GARR 6144      // bytes per tile (128*48)
#define GSTG 24576     // bytes per stage (4 tiles)
#define GSMEM 98304    // 4 stages
#define NCHUNK 64

__global__ __launch_bounds__(256, 2)
void gemm_mma(float* __restrict__ Cext, int wsel, int csel, float scale) {
    extern __shared__ char dsm[];

    const int tid = threadIdx.x;
    const int lane = tid & 31, warp = tid >> 5;
    const int wm = warp & 3, wn = warp >> 2;
    const int bx = blockIdx.x, by = blockIdx.y;   // (N/128=8, M/128=32)

    const __nv_bfloat16* wh = g_wh + (size_t)wsel * MM;
    const __nv_bfloat16* wl = g_wl + (size_t)wsel * MM;
    const size_t aoff = (size_t)by * 128 * 1024;
    const size_t woff = (size_t)bx * 128 * 1024;

    const int ldrow = tid >> 1;           // 0..127
    const int ldh = (tid & 1);            // 16B half of the 32B k16 row

    const uint32_t sb = smem_u32(dsm);
    const int arow = wm * 32 + (lane & 15);
    const int acol = ((lane >> 4) & 1) * 16;
    const int brow = wn * 64 + ((lane >> 4) & 1) * 8 + (lane & 7);
    const int bcol = ((lane >> 3) & 1) * 16;

    float c[2][8][4];
#pragma unroll
    for (int mt = 0; mt < 2; mt++)
#pragma unroll
        for (int nt = 0; nt < 8; nt++)
#pragma unroll
            for (int r = 0; r < 4; r++) c[mt][nt][r] = 0.0f;

#define ISSUE(CH) do {                                                           \
    int _st = (CH) & 3;                                                          \
    size_t _go = (size_t)ldrow * 1024 + (CH) * 16 + ldh * 8;                     \
    uint32_t _so = sb + _st * GSTG + ldrow * GSTR + ldh * 16;                    \
    cpasync16(_so,            g_ah + aoff + _go);                                \
    cpasync16(_so + GARR,     g_al + aoff + _go);                                \
    cpasync16(_so + 2 * GARR, wh + woff + _go);                                  \
    cpasync16(_so + 3 * GARR, wl + woff + _go);                                  \
    cp_commit();                                                                 \
} while (0)

    ISSUE(0); ISSUE(1); ISSUE(2);

    for (int it = 0; it < NCHUNK; it++) {
        if (it < NCHUNK - 2)       cp_wait2();
        else if (it == NCHUNK - 2) cp_wait1();
        else                       cp_wait0();
        __syncthreads();
        // prefetch into stage (it-1)&3: consumed by all warps before the barrier
        if (it + 3 < NCHUNK) ISSUE(it + 3);

        const uint32_t base = sb + (it & 3) * GSTG;
        uint32_t a4h[2][4], a4l[2][4], b4[8][2];
        // Wh fragments
#pragma unroll
        for (int nt2 = 0; nt2 < 4; nt2++) {
            uint32_t r[4];
            ldsm_x4(r, base + 2 * GARR + (uint32_t)(brow + nt2 * 16) * GSTR + bcol);
            b4[nt2 * 2][0] = r[0]; b4[nt2 * 2][1] = r[1];
            b4[nt2 * 2 + 1][0] = r[2]; b4[nt2 * 2 + 1][1] = r[3];
        }
        // Ah, Al fragments
#pragma unroll
        for (int mt = 0; mt < 2; mt++) {
            ldsm_x4(a4h[mt], base + (uint32_t)(arow + mt * 16) * GSTR + acol);
            ldsm_x4(a4l[mt], base + GARR + (uint32_t)(arow + mt * 16) * GSTR + acol);
        }
        // leg 1: Ah . Wh
#pragma unroll
        for (int mt = 0; mt < 2; mt++)
#pragma unroll
            for (int nt = 0; nt < 8; nt++) mma16816(c[mt][nt], a4h[mt], b4[nt]);
        // leg 2: Al . Wh
#pragma unroll
        for (int mt = 0; mt < 2; mt++)
#pragma unroll
            for (int nt = 0; nt < 8; nt++) mma16816(c[mt][nt], a4l[mt], b4[nt]);
        // leg 3: Ah . Wl (reuse a4h regs)
#pragma unroll
        for (int nt2 = 0; nt2 < 4; nt2++) {
            uint32_t r[4];
            ldsm_x4(r, base + 3 * GARR + (uint32_t)(brow + nt2 * 16) * GSTR + bcol);
            b4[nt2 * 2][0] = r[0]; b4[nt2 * 2][1] = r[1];
            b4[nt2 * 2 + 1][0] = r[2]; b4[nt2 * 2 + 1][1] = r[3];
        }
#pragma unroll
        for (int mt = 0; mt < 2; mt++)
#pragma unroll
            for (int nt = 0; nt < 8; nt++) mma16816(c[mt][nt], a4h[mt], b4[nt]);
    }
#undef ISSUE

    // epilogue
    const int g = lane >> 2, tg = lane & 3;
#pragma unroll
    for (int mt = 0; mt < 2; mt++) {
#pragma unroll
        for (int nt = 0; nt < 8; nt++) {
            int m = by * 128 + wm * 32 + mt * 16 + g;
            int n = bx * 128 + wn * 64 + nt * 8 + tg * 2;
            float v00 = c[mt][nt][0] * scale, v01 = c[mt][nt][1] * scale;
            float v10 = c[mt][nt][2] * scale, v11 = c[mt][nt][3] * scale;
            if (csel == 3) {
                *(float2*)(Cext + (size_t)m * 1024 + n) = make_float2(v00, v01);
                *(float2*)(Cext + (size_t)(m + 8) * 1024 + n) = make_float2(v10, v11);
            } else {
                __nv_bfloat16* Chi = (csel == 0) ? g_qh : (csel == 1 ? g_kh : g_vh);
                __nv_bfloat16* Clo = (csel == 0) ? g_ql : (csel == 1 ? g_kl : g_vl);
                int head = n >> 6, d = n & 63;
                int bbi = m >> 11, ssi = m & 2047;
                size_t base2 = (((size_t)bbi * Hn + head) * Sq + ssi) * Hd + d;
                __nv_bfloat162 h0 = __floats2bfloat162_rn(v00, v01);
                __nv_bfloat162 h1 = __floats2bfloat162_rn(v10, v11);
                __nv_bfloat162 l0 = __floats2bfloat162_rn(
                    v00 - __bfloat162float(h0.x), v01 - __bfloat162float(h0.y));
                __nv_bfloat162 l1 = __floats2bfloat162_rn(
                    v10 - __bfloat162float(h1.x), v11 - __bfloat162float(h1.y));
                *(__nv_bfloat162*)(Chi + base2) = h0;
                *(__nv_bfloat162*)(Chi + base2 + 8 * Hd) = h1;
                *(__nv_bfloat162*)(Clo + base2) = l0;
                *(__nv_bfloat162*)(Clo + base2 + 8 * Hd) = l1;
            }
        }
    }
}

// ---------------- flash attention: 8 warps, 128 queries/CTA ------------------
// K/V tiles (64 keys) shared by 2x the queries vs R11: half the global K/V
// traffic, barriers amortized over 8 warps. Same per-warp fragment math.
__global__ __launch_bounds__(256, 2)
void attn_mma(const float* __restrict__ relb) {
    __shared__ __nv_bfloat16 sKh[64][72];
    __shared__ __nv_bfloat16 sKl[64][72];
    __shared__ __nv_bfloat16 sVh[64][72];
    __shared__ __nv_bfloat16 sVl[64][72];
    __shared__ float biasf[2176];

    const int tid = threadIdx.x;
    const int lane = tid & 31, warp = tid >> 5;      // warp 0..7
    const int g = lane >> 2, tg = lane & 3;
    const int h = blockIdx.y, b = blockIdx.z;
    const int q0 = blockIdx.x * 128;

    const size_t bh = ((size_t)b * Hn + h) * Sq;
    const int ldrow = tid >> 2;           // 0..63 (4 threads per row)
    const int part = tid & 3;             // 16-element slice of the 64-d row

    const uint32_t khb = smem_u32(&sKh[0][0]);
    const uint32_t klb = smem_u32(&sKl[0][0]);
    const uint32_t vhb = smem_u32(&sVh[0][0]);
    const uint32_t vlb = smem_u32(&sVl[0][0]);

    const __nv_bfloat16* kh_g = g_kh + bh * Hd;
    const __nv_bfloat16* kl_g = g_kl + bh * Hd;
    const __nv_bfloat16* vh_g = g_vh + bh * Hd;
    const __nv_bfloat16* vl_g = g_vl + bh * Hd;

#define ISSK(KT) do {                                                            \
    size_t _go = (size_t)((KT) + ldrow) * Hd + part * 16;                        \
    uint32_t _so = ldrow * 144 + part * 32;                                      \
    cpasync16(khb + _so,      kh_g + _go);                                       \
    cpasync16(khb + _so + 16, kh_g + _go + 8);                                   \
    cpasync16(klb + _so,      kl_g + _go);                                       \
    cpasync16(klb + _so + 16, kl_g + _go + 8);                                   \
    cp_commit();                                                                 \
} while (0)

#define ISSV(KT) do {                                                            \
    size_t _go = (size_t)((KT) + ldrow) * Hd + part * 16;                        \
    uint32_t _so = ldrow * 144 + part * 32;                                      \
    cpasync16(vhb + _so,      vh_g + _go);                                       \
    cpasync16(vhb + _so + 16, vh_g + _go + 8);                                   \
    cpasync16(vlb + _so,      vl_g + _go);                                       \
    cpasync16(vlb + _so + 16, vl_g + _go + 8);                                   \
    cp_commit();                                                                 \
} while (0)

    ISSK(0);                               // K0 streams while Q stages

    // ---- stage Q (128 rows) through V buffers in two 64-row rounds ----
    uint32_t qh[4][4], ql[4][4];
    const __nv_bfloat16* qh_g = g_qh + (bh + q0) * Hd;
    const __nv_bfloat16* ql_g = g_ql + (bh + q0) * Hd;
    const uint32_t qoff = (uint32_t)((warp & 3) * 16 + (lane & 15)) * 144 + ((lane >> 4) & 1) * 16;
#pragma unroll
    for (int p = 0; p < 2; p++) {
        size_t go = (size_t)(p * 64 + ldrow) * Hd + part * 16;
        uint32_t so = ldrow * 144 + part * 32;
        *(uint4*)((char*)&sVh[0][0] + so)      = *(const uint4*)(qh_g + go);
        *(uint4*)((char*)&sVh[0][0] + so + 16) = *(const uint4*)(qh_g + go + 8);
        *(uint4*)((char*)&sVl[0][0] + so)      = *(const uint4*)(ql_g + go);
        *(uint4*)((char*)&sVl[0][0] + so + 16) = *(const uint4*)(ql_g + go + 8);
        __syncthreads();
        if ((warp >> 2) == p) {
#pragma unroll
            for (int ks = 0; ks < 4; ks++) {
                ldsm_x4(qh[ks], vhb + qoff + ks * 32);
                ldsm_x4(ql[ks], vlb + qoff + ks * 32);
            }
        }
        __syncthreads();
    }
    // bias table: biasf[j] = bias(key - q), j = key + 127 - (q - q0)
    for (int j = tid; j < 2176; j += 256)
        biasf[j] = relb[(int)g_bucket[j + 1920 - q0] * Hn + h];
    __syncthreads();
    ISSV(0);                               // pending groups: {K0, V0}

    float onn[8][4];
#pragma unroll
    for (int nt = 0; nt < 8; nt++)
#pragma unroll
        for (int r = 0; r < 4; r++) onn[nt][r] = 0.0f;
    float mrun0 = -1e30f, mrun1 = -1e30f, lr0 = 0.0f, lr1 = 0.0f;

    const int rg = warp * 16 + g;                      // block-local query row
    const uint32_t kRow = ((lane >> 4) & 1) * 8 + (lane & 7);
    const uint32_t kCol = ((lane >> 3) & 1) * 16;
    const uint32_t vRow = ((lane >> 3) & 1) * 8 + (lane & 7);
    const uint32_t vCol = (uint32_t)((lane >> 4) * 8) * 2;

    for (int ti = 0; ti < 32; ti++) {
        const int kt = ti * 64;
        cp_wait1();                        // K(ti) retired (FIFO)
        __syncthreads();

        // ---- QK: scores c[8][4] ----
        float c[8][4];
#pragma unroll
        for (int nt = 0; nt < 8; nt++)
#pragma unroll
            for (int r = 0; r < 4; r++) c[nt][r] = 0.0f;

        uint32_t bfr[8][2];
#pragma unroll
        for (int ks = 0; ks < 4; ks++) {
#pragma unroll
            for (int m = 0; m < 4; m++) {
                uint32_t t4[4];
                ldsm_x4(t4, khb + (uint32_t)(m * 16 + kRow) * 144 + kCol + ks * 32);
                bfr[2 * m][0] = t4[0]; bfr[2 * m][1] = t4[1];
                bfr[2 * m + 1][0] = t4[2]; bfr[2 * m + 1][1] = t4[3];
            }
#pragma unroll
            for (int nt = 0; nt < 8; nt++) mma16816(c[nt], qh[ks], bfr[nt]);
#pragma unroll
            for (int nt = 0; nt < 8; nt++) mma16816(c[nt], ql[ks], bfr[nt]);
#pragma unroll
            for (int m = 0; m < 4; m++) {
                uint32_t t4[4];
                ldsm_x4(t4, klb + (uint32_t)(m * 16 + kRow) * 144 + kCol + ks * 32);
                bfr[2 * m][0] = t4[0]; bfr[2 * m][1] = t4[1];
                bfr[2 * m + 1][0] = t4[2]; bfr[2 * m + 1][1] = t4[3];
            }
#pragma unroll
            for (int nt = 0; nt < 8; nt++) mma16816(c[nt], qh[ks], bfr[nt]);
        }
        __syncthreads();                   // all warps done reading K tiles
        if (ti < 31) ISSK(kt + 64);        // prefetch next K during softmax+PV

        // ---- bias ----
        const int jb = kt + 127 - rg + tg * 2;
#pragma unroll
        for (int nt = 0; nt < 8; nt++) {
            int j0 = jb + nt * 8;
            c[nt][0] += biasf[j0];
            c[nt][1] += biasf[j0 + 1];
            c[nt][2] += biasf[j0 - 8];
            c[nt][3] += biasf[j0 - 7];
        }

        // ---- online softmax (rows rg, rg+8; quad lanes share a row) ----
        float m0 = c[0][0], m1 = c[0][2];
#pragma unroll
        for (int nt = 0; nt < 8; nt++) {
            m0 = fmaxf(m0, fmaxf(c[nt][0], c[nt][1]));
            m1 = fmaxf(m1, fmaxf(c[nt][2], c[nt][3]));
        }
        m0 = fmaxf(m0, __shfl_xor_sync(0xffffffffu, m0, 1));
        m0 = fmaxf(m0, __shfl_xor_sync(0xffffffffu, m0, 2));
        m1 = fmaxf(m1, __shfl_xor_sync(0xffffffffu, m1, 1));
        m1 = fmaxf(m1, __shfl_xor_sync(0xffffffffu, m1, 2));
        float mn0 = fmaxf(mrun0, m0), mn1 = fmaxf(mrun1, m1);
        float sc0 = __expf(mrun0 - mn0), sc1 = __expf(mrun1 - mn1);
        mrun0 = mn0; mrun1 = mn1;
        lr0 *= sc0; lr1 *= sc1;
#pragma unroll
        for (int nt = 0; nt < 8; nt++) {
            onn[nt][0] *= sc0; onn[nt][1] *= sc0;
            onn[nt][2] *= sc1; onn[nt][3] *= sc1;
        }
#pragma unroll
        for (int nt = 0; nt < 8; nt++) {
            c[nt][0] = __expf(c[nt][0] - mn0);
            c[nt][1] = __expf(c[nt][1] - mn0);
            c[nt][2] = __expf(c[nt][2] - mn1);
            c[nt][3] = __expf(c[nt][3] - mn1);
            lr0 += c[nt][0] + c[nt][1];
            lr1 += c[nt][2] + c[nt][3];
        }

        // ---- P fragments (hi/lo) from score frags ----
        uint32_t ph[4][4], pl[4][4];
#pragma unroll
        for (int ks = 0; ks < 4; ks++) {
            const float* ce = c[2 * ks];
            const float* co = c[2 * ks + 1];
            __nv_bfloat162 h0 = __floats2bfloat162_rn(ce[0], ce[1]);
            __nv_bfloat162 h1 = __floats2bfloat162_rn(ce[2], ce[3]);
            __nv_bfloat162 h2 = __floats2bfloat162_rn(co[0], co[1]);
            __nv_bfloat162 h3 = __floats2bfloat162_rn(co[2], co[3]);
            ph[ks][0] = *(uint32_t*)&h0; ph[ks][1] = *(uint32_t*)&h1;
            ph[ks][2] = *(uint32_t*)&h2; ph[ks][3] = *(uint32_t*)&h3;
            pl[ks][0] = pack_bf2(ce[0] - __bfloat162float(h0.x), ce[1] - __bfloat162float(h0.y));
            pl[ks][1] = pack_bf2(ce[2] - __bfloat162float(h1.x), ce[3] - __bfloat162float(h1.y));
            pl[ks][2] = pack_bf2(co[0] - __bfloat162float(h2.x), co[1] - __bfloat162float(h2.y));
            pl[ks][3] = pack_bf2(co[2] - __bfloat162float(h3.x), co[3] - __bfloat162float(h3.y));
        }

        // V(ti) readiness: after the K(ti+1) commit, FIFO pending = {V(ti), K(ti+1)}
        if (ti < 31) cp_wait1(); else cp_wait0();
        __syncthreads();

        // ---- PV: O += Ph.Vh + Pl.Vh + Ph.Vl ----
#pragma unroll
        for (int ks = 0; ks < 4; ks++) {
#pragma unroll
            for (int n2 = 0; n2 < 4; n2++) {
                uint32_t t4[4];
                ldsm_x4_t(t4, vhb + (uint32_t)(ks * 16 + vRow) * 144 + (uint32_t)(n2 * 16) * 2 + vCol);
                bfr[2 * n2][0] = t4[0]; bfr[2 * n2][1] = t4[1];
                bfr[2 * n2 + 1][0] = t4[2]; bfr[2 * n2 + 1][1] = t4[3];
            }
#pragma unroll
            for (int nt = 0; nt < 8; nt++) mma16816(onn[nt], ph[ks], bfr[nt]);
#pragma unroll
            for (int nt = 0; nt < 8; nt++) mma16816(onn[nt], pl[ks], bfr[nt]);
#pragma unroll
            for (int n2 = 0; n2 < 4; n2++) {
                uint32_t t4[4];
                ldsm_x4_t(t4, vlb + (uint32_t)(ks * 16 + vRow) * 144 + (uint32_t)(n2 * 16) * 2 + vCol);
                bfr[2 * n2][0] = t4[0]; bfr[2 * n2][1] = t4[1];
                bfr[2 * n2 + 1][0] = t4[2]; bfr[2 * n2 + 1][1] = t4[3];
            }
#pragma unroll
            for (int nt = 0; nt < 8; nt++) mma16816(onn[nt], ph[ks], bfr[nt]);
        }
        __syncthreads();                   // all warps done reading V tiles
        if (ti < 31) ISSV(kt + 64);        // prefetch next V during next QK
    }
#undef ISSK
#undef ISSV

    // ---- finalize: full row sums, normalize, write hi/lo output ----
    lr0 += __shfl_xor_sync(0xffffffffu, lr0, 1);
    lr0 += __shfl_xor_sync(0xffffffffu, lr0, 2);
    lr1 += __shfl_xor_sync(0xffffffffu, lr1, 1);
    lr1 += __shfl_xor_sync(0xffffffffu, lr1, 2);
    float inv0 = 1.0f / lr0, inv1 = 1.0f / lr1;

    const size_t s0 = (size_t)q0 + rg;
    __nv_bfloat16* oh0 = g_ah + ((size_t)b * Sq + s0) * Dm + h * Hd;
    __nv_bfloat16* ol0 = g_al + ((size_t)b * Sq + s0) * Dm + h * Hd;
#pragma unroll
    for (int nt = 0; nt < 8; nt++) {
        int d = nt * 8 + tg * 2;
        float a0 = onn[nt][0] * inv0, a1 = onn[nt][1] * inv0;
        float b0 = onn[nt][2] * inv1, b1 = onn[nt][3] * inv1;
        __nv_bfloat162 h0 = __floats2bfloat162_rn(a0, a1);
        __nv_bfloat162 h1 = __floats2bfloat162_rn(b0, b1);
        *(__nv_bfloat162*)(oh0 + d) = h0;
        *(__nv_bfloat162*)(oh0 + 8 * Dm + d) = h1;
        __nv_bfloat162 l0 = __floats2bfloat162_rn(a0 - __bfloat162float(h0.x),
                                                  a1 - __bfloat162float(h0.y));
        __nv_bfloat162 l1 = __floats2bfloat162_rn(b0 - __bfloat162float(h1.x),
                                                  b1 - __bfloat162float(h1.y));
        *(__nv_bfloat162*)(ol0 + d) = l0;
        *(__nv_bfloat162*)(ol0 + 8 * Dm + d) = l1;
    }
}

// ---------------- launch -----------------------------------------------------
extern "C" void kernel_launch(void* const* d_in, const int* in_sizes, int n_in,
                              void* d_out, int out_size) {
    (void)in_sizes; (void)n_in; (void)out_size;
    const float* x  = (const float*)d_in[0];
    const float* wq = (const float*)d_in[1];
    const float* wk = (const float*)d_in[2];
    const float* wv = (const float*)d_in[3];
    const float* wo = (const float*)d_in[4];
    const float* rb = (const float*)d_in[5];
    float* out = (float*)d_out;

    cudaFuncSetAttribute(gemm_mma, cudaFuncAttributeMaxDynamicSharedMemorySize, GSMEM);

    // 1. bucket LUT
    lut_kernel<<<16, 256>>>();
    // 2. fused split of x + all weights into bf16 hi/lo
    splitall_kernel<<<8192, 256>>>(x, wq, wk, wv, wo);
    // 3-5. Q/K/V projections -> bf16 hi/lo [B,H,S,d] (Q fused with 1/8 scale)
    dim3 gg(Dm / 128, (Bb * Sq) / 128);   // (8, 32)
    gemm_mma<<<gg, 256, GSMEM>>>(nullptr, 0, 0, 0.125f);
    gemm_mma<<<gg, 256, GSMEM>>>(nullptr, 1, 1, 1.0f);
    gemm_mma<<<gg, 256, GSMEM>>>(nullptr, 2, 2, 1.0f);
    // 6. flash attention (mma.sync, 128 q/CTA) -> g_ah/g_al hi/lo
    attn_mma<<<dim3(Sq / 128, Hn, Bb), 256>>>(rb);
    // 7. past_bias -> second output region [1,H,S,S]
    bias_kernel<<<dim3(Sq, Hn), 512>>>(rb, out + (size_t)Bb * Sq * Dm);
    // 8. output projection -> first output region [B,S,D] fp32
    gemm_mma<<<gg, 256, GSMEM>>>(out, 3, 3, 1.0f);
}